// round 4
// baseline (speedup 1.0000x reference)
#include <cuda_runtime.h>
#include <math.h>

#define NN 1024
#define BBATCH 8
#define KNS 17
#define EPS 0.03f
#define CMARGIN 1.4f

__device__ float  gBuf[6][NN * NN];
__device__ double gVd[NN];
__device__ double gWd[NN];
__device__ double gLam;
__device__ float  gV32[NN];
__device__ float  gW32[NN];
__device__ float  gLmax;
__device__ float  gCval;
__device__ float  gD[BBATCH * NN];

// ---------------- elementwise / small kernels ----------------

__global__ void k_buildM(const float* __restrict__ Pu) {
    int idx = blockIdx.x * 256 + threadIdx.x;
    gBuf[0][idx] = 1024.0f * fabsf(Pu[idx]);
}

__global__ void k_init_v1() { gVd[threadIdx.x] = 1.0 / 32.0; }

// w = M v, fp64 accumulate (M = gBuf[0]); one warp per row
__global__ void k_gemv64() {
    int row  = blockIdx.x * 8 + (threadIdx.x >> 5);
    int lane = threadIdx.x & 31;
    const float* Arow = &gBuf[0][row * NN];
    double s = 0.0;
    #pragma unroll 8
    for (int j = lane; j < NN; j += 32) s += (double)Arow[j] * gVd[j];
    #pragma unroll
    for (int o = 16; o; o >>= 1) s += __shfl_xor_sync(0xffffffffu, s, o);
    if (lane == 0) gWd[row] = s;
}

__global__ void k_norm64() {
    int tid = threadIdx.x;
    double x = gWd[tid];
    double s = x * x;
    #pragma unroll
    for (int o = 16; o; o >>= 1) s += __shfl_xor_sync(0xffffffffu, s, o);
    __shared__ double red[32];
    if ((tid & 31) == 0) red[tid >> 5] = s;
    __syncthreads();
    if (tid < 32) {
        double t = red[tid];
        #pragma unroll
        for (int o = 16; o; o >>= 1) t += __shfl_xor_sync(0xffffffffu, t, o);
        if (tid == 0) red[0] = t;
    }
    __syncthreads();
    double nrm = sqrt(red[0]);
    gVd[tid] = x / nrm;
    if (tid == 0) gLam = nrm;
}

// M' = M - (lam1-eps) v v^T + eps*I  (in place on gBuf[0], fp64 math)
__global__ void k_deflate() {
    int idx = blockIdx.x * 256 + threadIdx.x;
    int n = idx >> 10, m = idx & (NN - 1);
    double val = (double)gBuf[0][idx] - (gLam - (double)EPS) * gVd[n] * gVd[m];
    if (n == m) val += (double)EPS;
    gBuf[0][idx] = (float)val;
}

__global__ void k_init_v2() {
    unsigned i = threadIdx.x;
    unsigned h = i * 2654435761u + 12345u;
    h ^= h >> 13; h *= 0x5bd1e995u; h ^= h >> 15;
    gV32[i] = (float)(h & 0xFFFFu) / 65536.0f - 0.5f;
}

__global__ void k_gemv32() {
    int row  = blockIdx.x * 8 + (threadIdx.x >> 5);
    int lane = threadIdx.x & 31;
    const float* Arow = &gBuf[0][row * NN];
    float s = 0.0f;
    #pragma unroll 8
    for (int j = lane; j < NN; j += 32) s += Arow[j] * gV32[j];
    #pragma unroll
    for (int o = 16; o; o >>= 1) s += __shfl_xor_sync(0xffffffffu, s, o);
    if (lane == 0) gW32[row] = s;
}

__global__ void k_norm32() {
    int tid = threadIdx.x;
    float x = gW32[tid];
    float s = x * x;
    #pragma unroll
    for (int o = 16; o; o >>= 1) s += __shfl_xor_sync(0xffffffffu, s, o);
    __shared__ float red[32];
    if ((tid & 31) == 0) red[tid >> 5] = s;
    __syncthreads();
    if (tid < 32) {
        float t = red[tid];
        #pragma unroll
        for (int o = 16; o; o >>= 1) t += __shfl_xor_sync(0xffffffffu, t, o);
        if (tid == 0) red[0] = t;
    }
    __syncthreads();
    float nrm = sqrtf(red[0]);
    gV32[tid] = x / nrm;
    if (tid == 0) gLmax = nrm;
}

// Y0 = M'/c into gBuf[1]; store c
__global__ void k_initY() {
    int idx = blockIdx.x * 256 + threadIdx.x;
    float c = CMARGIN * gLmax;
    gBuf[1][idx] = gBuf[0][idx] / c;
    if (idx == 0) gCval = c;
}

// G0 = 1.5I - 0.5*Y0   (iteration 1 shortcut since Z0 = I)
__global__ void k_lin1(int g, int y) {
    int idx = blockIdx.x * 256 + threadIdx.x;
    int n = idx >> 10, m = idx & (NN - 1);
    gBuf[g][idx] = ((n == m) ? 1.5f : 0.0f) - 0.5f * gBuf[y][idx];
}

// ---------------- SGEMM: C = alpha*A*B + diag*I ----------------
// BM=128, BN=64, BK=16, 256 threads, 8x4 accum, global->reg prefetch.

__device__ __forceinline__ void gemm_body(const float* __restrict__ A,
                                          const float* __restrict__ B,
                                          float* __restrict__ C,
                                          float alpha, float diag)
{
    __shared__ float As[16][128];
    __shared__ float Bs[16][64];
    const int tid  = threadIdx.x;
    const int bm   = blockIdx.y << 7;
    const int bn   = blockIdx.x << 6;

    const int arow = tid >> 2;          // 0..63
    const int acol = (tid & 3) << 2;    // 0,4,8,12
    const int brow = tid >> 4;          // 0..15
    const int bcol = (tid & 15) << 2;   // 0..60
    const int ty   = tid >> 4;          // 0..15 (m-group of 8)
    const int tx   = tid & 15;          // 0..15 (n-group of 4)

    const float* Aptr = A + (bm + arow) * NN + acol;
    const float* Bptr = B + brow * NN + bn + bcol;

    float4 a0 = *(const float4*)(Aptr);
    float4 a1 = *(const float4*)(Aptr + 64 * NN);
    float4 b0 = *(const float4*)(Bptr);

    float acc[8][4];
    #pragma unroll
    for (int i = 0; i < 8; i++)
        #pragma unroll
        for (int j = 0; j < 4; j++) acc[i][j] = 0.0f;

    for (int kt = 0; kt < NN; kt += 16) {
        As[acol + 0][arow]      = a0.x;
        As[acol + 1][arow]      = a0.y;
        As[acol + 2][arow]      = a0.z;
        As[acol + 3][arow]      = a0.w;
        As[acol + 0][arow + 64] = a1.x;
        As[acol + 1][arow + 64] = a1.y;
        As[acol + 2][arow + 64] = a1.z;
        As[acol + 3][arow + 64] = a1.w;
        *(float4*)&Bs[brow][bcol] = b0;
        __syncthreads();

        if (kt + 16 < NN) {
            a0 = *(const float4*)(Aptr + kt + 16);
            a1 = *(const float4*)(Aptr + 64 * NN + kt + 16);
            b0 = *(const float4*)(Bptr + (kt + 16) * NN);
        }

        #pragma unroll
        for (int k = 0; k < 16; k++) {
            float af[8], bf[4];
            *(float4*)&af[0] = *(const float4*)&As[k][ty << 3];
            *(float4*)&af[4] = *(const float4*)&As[k][(ty << 3) + 4];
            *(float4*)&bf[0] = *(const float4*)&Bs[k][tx << 2];
            #pragma unroll
            for (int i = 0; i < 8; i++)
                #pragma unroll
                for (int j = 0; j < 4; j++)
                    acc[i][j] = fmaf(af[i], bf[j], acc[i][j]);
        }
        __syncthreads();
    }

    const int gc = bn + (tx << 2);
    #pragma unroll
    for (int i = 0; i < 8; i++) {
        int gr = bm + (ty << 3) + i;
        float4 o;
        o.x = alpha * acc[i][0] + ((gr == gc    ) ? diag : 0.0f);
        o.y = alpha * acc[i][1] + ((gr == gc + 1) ? diag : 0.0f);
        o.z = alpha * acc[i][2] + ((gr == gc + 2) ? diag : 0.0f);
        o.w = alpha * acc[i][3] + ((gr == gc + 3) ? diag : 0.0f);
        *(float4*)(C + (size_t)gr * NN + gc) = o;
    }
}

__global__ void __launch_bounds__(256)
k_gemm(int ia, int ib, int ic, float alpha, float diag) {
    gemm_body(gBuf[ia], gBuf[ib], gBuf[ic], alpha, diag);
}

// batched pair: z=0 -> C0 = A0*B0 ; z=1 -> C1 = A1*B1
__global__ void __launch_bounds__(256)
k_gemm_pair(int ia0, int ib0, int ic0, int ia1, int ib1, int ic1) {
    const float* A = gBuf[blockIdx.z ? ia1 : ia0];
    const float* B = gBuf[blockIdx.z ? ib1 : ib0];
    float*       C = gBuf[blockIdx.z ? ic1 : ic0];
    gemm_body(A, B, C, 1.0f, 0.0f);
}

// ---------------- outputs ----------------

__global__ void k_d(const float* __restrict__ x) {
    int idx = blockIdx.x * 256 + threadIdx.x;   // BBATCH*NN
    gD[idx] = x[idx & (NN - 1)] - x[idx];
}

// P_k[b] = d_b d_b^T + |P_u| + 0.01*Q^2
__global__ void k_out1(const float* __restrict__ Pu, const float* __restrict__ Qk,
                       float* __restrict__ out) {
    int idx = blockIdx.x * 256 + threadIdx.x;   // NN*NN
    int n = idx >> 10, m = idx & (NN - 1);
    float q = Qk[idx];
    float base = fabsf(Pu[idx]) + 0.01f * q * q;
    #pragma unroll
    for (int b = 0; b < BBATCH; b++)
        out[(size_t)b * NN * NN + idx] = base + gD[b * NN + n] * gD[b * NN + m];
}

// sigma^T[0,b,i,n] = x_b[n] +/- p[i,n]
// p = av*v v^T + sqrt(c)*Y - (eps/2)*Z/sqrt(c)
__global__ void k_out2(const float* __restrict__ x, float* __restrict__ out,
                       int iy, int iz) {
    int idx = blockIdx.x * 256 + threadIdx.x;   // NN*NN, idx = i*NN+n
    int i = idx >> 10, n = idx & (NN - 1);
    float c   = gCval;
    float sqc = sqrtf(c);
    float s2e = sqrtf(2.0f * EPS);
    float av  = sqrtf((float)gLam) - (s2e - EPS / (2.0f * s2e));
    float pv  = av * (float)(gVd[i] * gVd[n])
              + sqc * gBuf[iy][idx]
              - (EPS * 0.5f / sqc) * gBuf[iz][idx];
    #pragma unroll
    for (int b = 0; b < BBATCH; b++) {
        float xb = x[b * NN + n];
        size_t base = (size_t)b * 2 * NN * NN;
        out[base + (size_t)i * NN + n]        = xb + pv;
        out[base + (size_t)(i + NN) * NN + n] = xb - pv;
    }
}

// ---------------- host ----------------

extern "C" void kernel_launch(void* const* d_in, const int* in_sizes, int n_in,
                              void* d_out, int out_size) {
    const float* x  = (const float*)d_in[0];   // [1,8,1024,1]
    const float* Pu = (const float*)d_in[1];   // [1024,1024]
    const float* Qk = (const float*)d_in[2];   // [1024,1024]
    float* out1 = (float*)d_out;               // P_k [8,1024,1024]
    float* out2 = out1 + (size_t)BBATCH * NN * NN;  // sigma^T [1,8,2048,1024]

    const int EW = NN * NN / 256;              // 4096 blocks
    dim3 gg(NN / 64, NN / 128);                // (16,8)
    dim3 gp(NN / 64, NN / 128, 2);

    // M = N*|P_u|
    k_buildM<<<EW, 256>>>(Pu);

    // Perron pair (fp64)
    k_init_v1<<<1, NN>>>();
    for (int it = 0; it < 6; it++) {
        k_gemv64<<<NN / 8, 256>>>();
        k_norm64<<<1, NN>>>();
    }
    k_deflate<<<EW, 256>>>();

    // lambda_max(M') (fp32)
    k_init_v2<<<1, NN>>>();
    for (int it = 0; it < 16; it++) {
        k_gemv32<<<NN / 8, 256>>>();
        k_norm32<<<1, NN>>>();
    }
    k_initY<<<EW, 256>>>();

    // Newton-Schulz: Y->A^{1/2}, Z->A^{-1/2}
    int Y = 1, Z;
    // iter 1 (Z0 = I): G0 elementwise, Y1 = Y0*G0, Z1 = G0
    k_lin1<<<EW, 256>>>(3, 1);
    k_gemm<<<gg, 256>>>(1, 3, 4, 1.0f, 0.0f);
    Y = 4; Z = 3;
    int f0 = 0, f1 = 1, f2 = 2;
    for (int it = 2; it <= KNS; it++) {
        int G = f0;
        k_gemm<<<gg, 256>>>(Z, Y, G, -0.5f, 1.5f);   // G = 1.5I - 0.5*Z*Y
        if (it < KNS) {
            int Yn = f1, Zn = f2;
            k_gemm_pair<<<gp, 256>>>(Y, G, Yn, G, Z, Zn);
            f0 = Y; f1 = Z; f2 = G;
            Y = Yn; Z = Zn;
        } else {
            int Yn = f1;
            k_gemm<<<gg, 256>>>(Y, G, Yn, 1.0f, 0.0f);
            Y = Yn;                                   // Z stays Z_{K-1}
        }
    }

    // outputs
    k_d<<<BBATCH * NN / 256, 256>>>(x);
    k_out1<<<EW, 256>>>(Pu, Qk, out1);
    k_out2<<<EW, 256>>>(x, out2, Y, Z);
}

// round 5
// speedup vs baseline: 1.3034x; 1.3034x over previous
#include <cuda_runtime.h>
#include <math.h>

#define NN 1024
#define BBATCH 8
#define KNS 12
#define EPS 0.015f
#define CMARGIN 1.4f

__device__ float  gBuf[6][NN * NN];
__device__ double gVd[NN];
__device__ double gWd[NN];
__device__ double gLam;
__device__ float  gV32[NN];
__device__ float  gW32[NN];
__device__ float  gLmax;
__device__ float  gCval;
__device__ float  gS[KNS];
__device__ float  gD[BBATCH * NN];

// ---------------- elementwise / small kernels ----------------

__global__ void k_buildM(const float* __restrict__ Pu) {
    int idx = blockIdx.x * 256 + threadIdx.x;
    gBuf[0][idx] = 1024.0f * fabsf(Pu[idx]);
}

__global__ void k_init_v1() { gVd[threadIdx.x] = 1.0 / 32.0; }

// w = M v, fp64 accumulate (M = gBuf[0]); one warp per row
__global__ void k_gemv64() {
    int row  = blockIdx.x * 8 + (threadIdx.x >> 5);
    int lane = threadIdx.x & 31;
    const float* Arow = &gBuf[0][row * NN];
    double s = 0.0;
    #pragma unroll 8
    for (int j = lane; j < NN; j += 32) s += (double)Arow[j] * gVd[j];
    #pragma unroll
    for (int o = 16; o; o >>= 1) s += __shfl_xor_sync(0xffffffffu, s, o);
    if (lane == 0) gWd[row] = s;
}

__global__ void k_norm64() {
    int tid = threadIdx.x;
    double x = gWd[tid];
    double s = x * x;
    #pragma unroll
    for (int o = 16; o; o >>= 1) s += __shfl_xor_sync(0xffffffffu, s, o);
    __shared__ double red[32];
    if ((tid & 31) == 0) red[tid >> 5] = s;
    __syncthreads();
    if (tid < 32) {
        double t = red[tid];
        #pragma unroll
        for (int o = 16; o; o >>= 1) t += __shfl_xor_sync(0xffffffffu, t, o);
        if (tid == 0) red[0] = t;
    }
    __syncthreads();
    double nrm = sqrt(red[0]);
    gVd[tid] = x / nrm;
    if (tid == 0) gLam = nrm;
}

// M' = M - (lam1-eps) v v^T + eps*I  (in place on gBuf[0], fp64 math)
__global__ void k_deflate() {
    int idx = blockIdx.x * 256 + threadIdx.x;
    int n = idx >> 10, m = idx & (NN - 1);
    double val = (double)gBuf[0][idx] - (gLam - (double)EPS) * gVd[n] * gVd[m];
    if (n == m) val += (double)EPS;
    gBuf[0][idx] = (float)val;
}

__global__ void k_init_v2() {
    unsigned i = threadIdx.x;
    unsigned h = i * 2654435761u + 12345u;
    h ^= h >> 13; h *= 0x5bd1e995u; h ^= h >> 15;
    gV32[i] = (float)(h & 0xFFFFu) / 65536.0f - 0.5f;
}

__global__ void k_gemv32() {
    int row  = blockIdx.x * 8 + (threadIdx.x >> 5);
    int lane = threadIdx.x & 31;
    const float* Arow = &gBuf[0][row * NN];
    float s = 0.0f;
    #pragma unroll 8
    for (int j = lane; j < NN; j += 32) s += Arow[j] * gV32[j];
    #pragma unroll
    for (int o = 16; o; o >>= 1) s += __shfl_xor_sync(0xffffffffu, s, o);
    if (lane == 0) gW32[row] = s;
}

__global__ void k_norm32() {
    int tid = threadIdx.x;
    float x = gW32[tid];
    float s = x * x;
    #pragma unroll
    for (int o = 16; o; o >>= 1) s += __shfl_xor_sync(0xffffffffu, s, o);
    __shared__ float red[32];
    if ((tid & 31) == 0) red[tid >> 5] = s;
    __syncthreads();
    if (tid < 32) {
        float t = red[tid];
        #pragma unroll
        for (int o = 16; o; o >>= 1) t += __shfl_xor_sync(0xffffffffu, t, o);
        if (tid == 0) red[0] = t;
    }
    __syncthreads();
    float nrm = sqrtf(red[0]);
    gV32[tid] = x / nrm;
    if (tid == 0) gLmax = nrm;
}

// Y0 = M'/c into gBuf[1]; store c
__global__ void k_initY() {
    int idx = blockIdx.x * 256 + threadIdx.x;
    float c = CMARGIN * gLmax;
    gBuf[1][idx] = gBuf[0][idx] / c;
    if (idx == 0) gCval = c;
}

// Optimal scaling schedule: interval [a,b] of W-spectrum; equalize f(sa)=f(sb)
// with f(w)=w(3-w)^2/4 via bisection on s in [1/b, ~3/b). Single thread.
__global__ void k_sched() {
    double a = 0.9 * (double)EPS / (double)gCval;
    double b = 0.80;   // conservative upper bound incl. lambda_max underestimate margin
    for (int k = 0; k < KNS; k++) {
        double lo = 1.0 / b, hi = 2.9999 / b;
        for (int t = 0; t < 60; t++) {
            double s  = 0.5 * (lo + hi);
            double fa = s * a * (3.0 - s * a) * (3.0 - s * a) * 0.25;
            double fb = s * b * (3.0 - s * b) * (3.0 - s * b) * 0.25;
            if (fa < fb) lo = s; else hi = s;
        }
        double s = 0.5 * (lo + hi);
        gS[k] = (float)s;
        double sa = s * a, sb = s * b;
        double fa = sa * (3.0 - sa) * (3.0 - sa) * 0.25;
        double fb = sb * (3.0 - sb) * (3.0 - sb) * 0.25;
        a = fmin(fa, fb);
        b = (sa <= 1.0 && 1.0 <= sb) ? 1.0 : fmax(fa, fb);
        if (a > b) { double tmp = a; a = b; b = tmp; }
    }
}

// Iter-1 shortcut (Z0 = I): G = sqrt(s)*(1.5I - 0.5*s*Y0), elementwise
__global__ void k_lin1(int g, int y) {
    int idx = blockIdx.x * 256 + threadIdx.x;
    int n = idx >> 10, m = idx & (NN - 1);
    float s  = gS[0];
    float sq = sqrtf(s);
    gBuf[g][idx] = sq * (((n == m) ? 1.5f : 0.0f) - 0.5f * s * gBuf[y][idx]);
}

// ---------------- SGEMM: C = alpha*A*B + diag*I ----------------
// BM=128, BN=64, BK=16, 256 threads, 8x4 accum, global->reg prefetch.

__device__ __forceinline__ void gemm_body(const float* __restrict__ A,
                                          const float* __restrict__ B,
                                          float* __restrict__ C,
                                          float alpha, float diag)
{
    __shared__ float As[16][128];
    __shared__ float Bs[16][64];
    const int tid  = threadIdx.x;
    const int bm   = blockIdx.y << 7;
    const int bn   = blockIdx.x << 6;

    const int arow = tid >> 2;          // 0..63
    const int acol = (tid & 3) << 2;    // 0,4,8,12
    const int brow = tid >> 4;          // 0..15
    const int bcol = (tid & 15) << 2;   // 0..60
    const int ty   = tid >> 4;          // 0..15 (m-group of 8)
    const int tx   = tid & 15;          // 0..15 (n-group of 4)

    const float* Aptr = A + (bm + arow) * NN + acol;
    const float* Bptr = B + brow * NN + bn + bcol;

    float4 a0 = *(const float4*)(Aptr);
    float4 a1 = *(const float4*)(Aptr + 64 * NN);
    float4 b0 = *(const float4*)(Bptr);

    float acc[8][4];
    #pragma unroll
    for (int i = 0; i < 8; i++)
        #pragma unroll
        for (int j = 0; j < 4; j++) acc[i][j] = 0.0f;

    for (int kt = 0; kt < NN; kt += 16) {
        As[acol + 0][arow]      = a0.x;
        As[acol + 1][arow]      = a0.y;
        As[acol + 2][arow]      = a0.z;
        As[acol + 3][arow]      = a0.w;
        As[acol + 0][arow + 64] = a1.x;
        As[acol + 1][arow + 64] = a1.y;
        As[acol + 2][arow + 64] = a1.z;
        As[acol + 3][arow + 64] = a1.w;
        *(float4*)&Bs[brow][bcol] = b0;
        __syncthreads();

        if (kt + 16 < NN) {
            a0 = *(const float4*)(Aptr + kt + 16);
            a1 = *(const float4*)(Aptr + 64 * NN + kt + 16);
            b0 = *(const float4*)(Bptr + (kt + 16) * NN);
        }

        #pragma unroll
        for (int k = 0; k < 16; k++) {
            float af[8], bf[4];
            *(float4*)&af[0] = *(const float4*)&As[k][ty << 3];
            *(float4*)&af[4] = *(const float4*)&As[k][(ty << 3) + 4];
            *(float4*)&bf[0] = *(const float4*)&Bs[k][tx << 2];
            #pragma unroll
            for (int i = 0; i < 8; i++)
                #pragma unroll
                for (int j = 0; j < 4; j++)
                    acc[i][j] = fmaf(af[i], bf[j], acc[i][j]);
        }
        __syncthreads();
    }

    const int gc = bn + (tx << 2);
    #pragma unroll
    for (int i = 0; i < 8; i++) {
        int gr = bm + (ty << 3) + i;
        float4 o;
        o.x = alpha * acc[i][0] + ((gr == gc    ) ? diag : 0.0f);
        o.y = alpha * acc[i][1] + ((gr == gc + 1) ? diag : 0.0f);
        o.z = alpha * acc[i][2] + ((gr == gc + 2) ? diag : 0.0f);
        o.w = alpha * acc[i][3] + ((gr == gc + 3) ? diag : 0.0f);
        *(float4*)(C + (size_t)gr * NN + gc) = o;
    }
}

// sidx >= 0: scaled-G mode -> alpha = -0.5*s^1.5, diag = 1.5*sqrt(s) from gS[sidx]
__global__ void __launch_bounds__(256)
k_gemm(int ia, int ib, int ic, float alpha, float diag, int sidx) {
    float al = alpha, dg = diag;
    if (sidx >= 0) {
        float s  = gS[sidx];
        float sq = sqrtf(s);
        al = -0.5f * s * sq;
        dg = 1.5f * sq;
    }
    gemm_body(gBuf[ia], gBuf[ib], gBuf[ic], al, dg);
}

// batched pair: z=0 -> C0 = A0*B0 ; z=1 -> C1 = A1*B1
__global__ void __launch_bounds__(256)
k_gemm_pair(int ia0, int ib0, int ic0, int ia1, int ib1, int ic1) {
    const float* A = gBuf[blockIdx.z ? ia1 : ia0];
    const float* B = gBuf[blockIdx.z ? ib1 : ib0];
    float*       C = gBuf[blockIdx.z ? ic1 : ic0];
    gemm_body(A, B, C, 1.0f, 0.0f);
}

// ---------------- outputs ----------------

__global__ void k_d(const float* __restrict__ x) {
    int idx = blockIdx.x * 256 + threadIdx.x;   // BBATCH*NN
    gD[idx] = x[idx & (NN - 1)] - x[idx];
}

// P_k[b] = d_b d_b^T + |P_u| + 0.01*Q^2
__global__ void k_out1(const float* __restrict__ Pu, const float* __restrict__ Qk,
                       float* __restrict__ out) {
    int idx = blockIdx.x * 256 + threadIdx.x;   // NN*NN
    int n = idx >> 10, m = idx & (NN - 1);
    float q = Qk[idx];
    float base = fabsf(Pu[idx]) + 0.01f * q * q;
    #pragma unroll
    for (int b = 0; b < BBATCH; b++)
        out[(size_t)b * NN * NN + idx] = base + gD[b * NN + n] * gD[b * NN + m];
}

// sigma^T[0,b,i,n] = x_b[n] +/- p[i,n]
// p = av*v v^T + sqrt(c)*Y - (eps/2)*Z/sqrt(c)
__global__ void k_out2(const float* __restrict__ x, float* __restrict__ out,
                       int iy, int iz) {
    int idx = blockIdx.x * 256 + threadIdx.x;   // NN*NN, idx = i*NN+n
    int i = idx >> 10, n = idx & (NN - 1);
    float c   = gCval;
    float sqc = sqrtf(c);
    float s2e = sqrtf(2.0f * EPS);
    float av  = sqrtf((float)gLam) - (s2e - EPS / (2.0f * s2e));
    float pv  = av * (float)(gVd[i] * gVd[n])
              + sqc * gBuf[iy][idx]
              - (EPS * 0.5f / sqc) * gBuf[iz][idx];
    #pragma unroll
    for (int b = 0; b < BBATCH; b++) {
        float xb = x[b * NN + n];
        size_t base = (size_t)b * 2 * NN * NN;
        out[base + (size_t)i * NN + n]        = xb + pv;
        out[base + (size_t)(i + NN) * NN + n] = xb - pv;
    }
}

// ---------------- host ----------------

extern "C" void kernel_launch(void* const* d_in, const int* in_sizes, int n_in,
                              void* d_out, int out_size) {
    const float* x  = (const float*)d_in[0];   // [1,8,1024,1]
    const float* Pu = (const float*)d_in[1];   // [1024,1024]
    const float* Qk = (const float*)d_in[2];   // [1024,1024]
    float* out1 = (float*)d_out;               // P_k [8,1024,1024]
    float* out2 = out1 + (size_t)BBATCH * NN * NN;  // sigma^T [1,8,2048,1024]

    const int EW = NN * NN / 256;              // 4096 blocks
    dim3 gg(NN / 64, NN / 128);                // (16,8)
    dim3 gp(NN / 64, NN / 128, 2);

    // M = N*|P_u|
    k_buildM<<<EW, 256>>>(Pu);

    // Perron pair (fp64); all-ones start has ~0.999 overlap with Perron vector
    k_init_v1<<<1, NN>>>();
    for (int it = 0; it < 4; it++) {
        k_gemv64<<<NN / 8, 256>>>();
        k_norm64<<<1, NN>>>();
    }
    k_deflate<<<EW, 256>>>();

    // lambda_max(M') estimate (fp32); schedule carries margin for underestimate
    k_init_v2<<<1, NN>>>();
    for (int it = 0; it < 10; it++) {
        k_gemv32<<<NN / 8, 256>>>();
        k_norm32<<<1, NN>>>();
    }
    k_initY<<<EW, 256>>>();
    k_sched<<<1, 1>>>();

    // Scaled Newton-Schulz: Y->A^{1/2}, Z->A^{-1/2}
    // iter 1 (Z0 = I): G elementwise, Y1 = Y0*G, Z1 = G
    k_lin1<<<EW, 256>>>(3, 1);
    k_gemm<<<gg, 256>>>(1, 3, 4, 1.0f, 0.0f, -1);
    int Y = 4, Z = 3;
    int f0 = 0, f1 = 1, f2 = 2;
    for (int it = 2; it <= KNS; it++) {
        int G = f0;
        // G = sqrt(s)*(1.5I - 0.5*s*Z*Y)
        k_gemm<<<gg, 256>>>(Z, Y, G, 0.0f, 0.0f, it - 1);
        if (it < KNS) {
            int Yn = f1, Zn = f2;
            k_gemm_pair<<<gp, 256>>>(Y, G, Yn, G, Z, Zn);
            f0 = Y; f1 = Z; f2 = G;
            Y = Yn; Z = Zn;
        } else {
            int Yn = f1;
            k_gemm<<<gg, 256>>>(Y, G, Yn, 1.0f, 0.0f, -1);
            Y = Yn;                                   // Z stays Z_{K-1} (converged)
        }
    }

    // outputs
    k_d<<<BBATCH * NN / 256, 256>>>(x);
    k_out1<<<EW, 256>>>(Pu, Qk, out1);
    k_out2<<<EW, 256>>>(x, out2, Y, Z);
}

// round 9
// speedup vs baseline: 1.4210x; 1.0902x over previous
#include <cuda_runtime.h>
#include <math.h>

#define NN 1024
#define BBATCH 8
#define KNS 11
#define EPS 0.015f
#define CMARGIN 1.4f

__device__ float  gBuf[6][NN * NN];
__device__ double gVd[NN];
__device__ double gWd[NN];
__device__ double gLam;
__device__ float  gV32[NN];
__device__ float  gW32[NN];
__device__ float  gLmax;
__device__ float  gCval;
__device__ float  gS[KNS];
__device__ float  gD[BBATCH * NN];

// ---------------- elementwise / small kernels ----------------

__global__ void k_buildM(const float* __restrict__ Pu) {
    int idx = blockIdx.x * 256 + threadIdx.x;
    gBuf[0][idx] = 1024.0f * fabsf(Pu[idx]);
}

__global__ void k_init_v1() { gVd[threadIdx.x] = 1.0 / 32.0; }

// w = M v, fp64 accumulate (M = gBuf[0]); one warp per row
__global__ void k_gemv64() {
    int row  = blockIdx.x * 8 + (threadIdx.x >> 5);
    int lane = threadIdx.x & 31;
    const float* Arow = &gBuf[0][row * NN];
    double s = 0.0;
    #pragma unroll 8
    for (int j = lane; j < NN; j += 32) s += (double)Arow[j] * gVd[j];
    #pragma unroll
    for (int o = 16; o; o >>= 1) s += __shfl_xor_sync(0xffffffffu, s, o);
    if (lane == 0) gWd[row] = s;
}

// normalize gWd -> gVd, gLam = ||gWd||
__global__ void k_norm64() {
    int tid = threadIdx.x;
    double x = gWd[tid];
    double s = x * x;
    #pragma unroll
    for (int o = 16; o; o >>= 1) s += __shfl_xor_sync(0xffffffffu, s, o);
    __shared__ double red[32];
    if ((tid & 31) == 0) red[tid >> 5] = s;
    __syncthreads();
    if (tid < 32) {
        double t = red[tid];
        #pragma unroll
        for (int o = 16; o; o >>= 1) t += __shfl_xor_sync(0xffffffffu, t, o);
        if (tid == 0) red[0] = t;
    }
    __syncthreads();
    double nrm = sqrt(red[0]);
    gVd[tid] = x / nrm;
    if (tid == 0) gLam = nrm;
}

// M' = M - (lam1-eps) v v^T + eps*I  (in place on gBuf[0], fp64 math)
__global__ void k_deflate() {
    int idx = blockIdx.x * 256 + threadIdx.x;
    int n = idx >> 10, m = idx & (NN - 1);
    double val = (double)gBuf[0][idx] - (gLam - (double)EPS) * gVd[n] * gVd[m];
    if (n == m) val += (double)EPS;
    gBuf[0][idx] = (float)val;
}

__global__ void k_init_v2() {
    unsigned i = threadIdx.x;
    unsigned h = i * 2654435761u + 12345u;
    h ^= h >> 13; h *= 0x5bd1e995u; h ^= h >> 15;
    gV32[i] = (float)(h & 0xFFFFu) / 65536.0f - 0.5f;
}

__global__ void k_gemv32() {
    int row  = blockIdx.x * 8 + (threadIdx.x >> 5);
    int lane = threadIdx.x & 31;
    const float* Arow = &gBuf[0][row * NN];
    float s = 0.0f;
    #pragma unroll 8
    for (int j = lane; j < NN; j += 32) s += Arow[j] * gV32[j];
    #pragma unroll
    for (int o = 16; o; o >>= 1) s += __shfl_xor_sync(0xffffffffu, s, o);
    if (lane == 0) gW32[row] = s;
}

// normalize gW32 -> gV32, gLmax = ||gW32||
__global__ void k_norm32() {
    int tid = threadIdx.x;
    float x = gW32[tid];
    float s = x * x;
    #pragma unroll
    for (int o = 16; o; o >>= 1) s += __shfl_xor_sync(0xffffffffu, s, o);
    __shared__ float red[32];
    if ((tid & 31) == 0) red[tid >> 5] = s;
    __syncthreads();
    if (tid < 32) {
        float t = red[tid];
        #pragma unroll
        for (int o = 16; o; o >>= 1) t += __shfl_xor_sync(0xffffffffu, t, o);
        if (tid == 0) red[0] = t;
    }
    __syncthreads();
    float nrm = sqrtf(red[0]);
    gV32[tid] = x / nrm;
    if (tid == 0) gLmax = nrm;
}

// Y0 = M'/c into gBuf[1]; store c
__global__ void k_initY() {
    int idx = blockIdx.x * 256 + threadIdx.x;
    float c = CMARGIN * gLmax;
    gBuf[1][idx] = gBuf[0][idx] / c;
    if (idx == 0) gCval = c;
}

// Optimal scaling schedule via single-thread bisection on f(w)=w(3-w)^2/4
__global__ void k_sched() {
    double a = 0.9 * (double)EPS / (double)gCval;
    double b = 0.80;   // conservative upper bound incl. lambda_max underestimate margin
    for (int k = 0; k < KNS; k++) {
        double lo = 1.0 / b, hi = 2.9999 / b;
        for (int t = 0; t < 60; t++) {
            double s  = 0.5 * (lo + hi);
            double fa = s * a * (3.0 - s * a) * (3.0 - s * a) * 0.25;
            double fb = s * b * (3.0 - s * b) * (3.0 - s * b) * 0.25;
            if (fa < fb) lo = s; else hi = s;
        }
        double s = 0.5 * (lo + hi);
        gS[k] = (float)s;
        double sa = s * a, sb = s * b;
        double fa = sa * (3.0 - sa) * (3.0 - sa) * 0.25;
        double fb = sb * (3.0 - sb) * (3.0 - sb) * 0.25;
        a = fmin(fa, fb);
        b = (sa <= 1.0 && 1.0 <= sb) ? 1.0 : fmax(fa, fb);
        if (a > b) { double tmp = a; a = b; b = tmp; }
    }
}

// Iter-1 shortcut (Z0 = I): G = sqrt(s)*(1.5I - 0.5*s*Y0), elementwise (full matrix)
__global__ void k_lin1(int g, int y) {
    int idx = blockIdx.x * 256 + threadIdx.x;
    int n = idx >> 10, m = idx & (NN - 1);
    float s  = gS[0];
    float sq = sqrtf(s);
    gBuf[g][idx] = sq * (((n == m) ? 1.5f : 0.0f) - 0.5f * s * gBuf[y][idx]);
}

// ---------------- SGEMM: C = alpha*A*B + diag*I ----------------
// BM=128, BN=64, BK=16, 256 threads, 8x4 accum, global->reg prefetch.

__device__ __forceinline__ void gemm_body(const float* __restrict__ A,
                                          const float* __restrict__ B,
                                          float* __restrict__ C,
                                          float alpha, float diag)
{
    __shared__ float As[16][128];
    __shared__ float Bs[16][64];
    const int tid  = threadIdx.x;
    const int bm   = blockIdx.y << 7;
    const int bn   = blockIdx.x << 6;

    const int arow = tid >> 2;          // 0..63
    const int acol = (tid & 3) << 2;    // 0,4,8,12
    const int brow = tid >> 4;          // 0..15
    const int bcol = (tid & 15) << 2;   // 0..60
    const int ty   = tid >> 4;          // 0..15 (m-group of 8)
    const int tx   = tid & 15;          // 0..15 (n-group of 4)

    const float* Aptr = A + (bm + arow) * NN + acol;
    const float* Bptr = B + brow * NN + bn + bcol;

    float4 a0 = *(const float4*)(Aptr);
    float4 a1 = *(const float4*)(Aptr + 64 * NN);
    float4 b0 = *(const float4*)(Bptr);

    float acc[8][4];
    #pragma unroll
    for (int i = 0; i < 8; i++)
        #pragma unroll
        for (int j = 0; j < 4; j++) acc[i][j] = 0.0f;

    for (int kt = 0; kt < NN; kt += 16) {
        As[acol + 0][arow]      = a0.x;
        As[acol + 1][arow]      = a0.y;
        As[acol + 2][arow]      = a0.z;
        As[acol + 3][arow]      = a0.w;
        As[acol + 0][arow + 64] = a1.x;
        As[acol + 1][arow + 64] = a1.y;
        As[acol + 2][arow + 64] = a1.z;
        As[acol + 3][arow + 64] = a1.w;
        *(float4*)&Bs[brow][bcol] = b0;
        __syncthreads();

        if (kt + 16 < NN) {
            a0 = *(const float4*)(Aptr + kt + 16);
            a1 = *(const float4*)(Aptr + 64 * NN + kt + 16);
            b0 = *(const float4*)(Bptr + (kt + 16) * NN);
        }

        #pragma unroll
        for (int k = 0; k < 16; k++) {
            float af[8], bf[4];
            *(float4*)&af[0] = *(const float4*)&As[k][ty << 3];
            *(float4*)&af[4] = *(const float4*)&As[k][(ty << 3) + 4];
            *(float4*)&bf[0] = *(const float4*)&Bs[k][tx << 2];
            #pragma unroll
            for (int i = 0; i < 8; i++)
                #pragma unroll
                for (int j = 0; j < 4; j++)
                    acc[i][j] = fmaf(af[i], bf[j], acc[i][j]);
        }
        __syncthreads();
    }

    const int gc = bn + (tx << 2);
    #pragma unroll
    for (int i = 0; i < 8; i++) {
        int gr = bm + (ty << 3) + i;
        float4 o;
        o.x = alpha * acc[i][0] + ((gr == gc    ) ? diag : 0.0f);
        o.y = alpha * acc[i][1] + ((gr == gc + 1) ? diag : 0.0f);
        o.z = alpha * acc[i][2] + ((gr == gc + 2) ? diag : 0.0f);
        o.w = alpha * acc[i][3] + ((gr == gc + 3) ? diag : 0.0f);
        *(float4*)(C + (size_t)gr * NN + gc) = o;
    }
}

// sidx >= 0: scaled-G mode -> alpha = -0.5*s^1.5, diag = 1.5*sqrt(s) from gS[sidx]
__global__ void __launch_bounds__(256)
k_gemm(int ia, int ib, int ic, float alpha, float diag, int sidx) {
    float al = alpha, dg = diag;
    if (sidx >= 0) {
        float s  = gS[sidx];
        float sq = sqrtf(s);
        al = -0.5f * s * sq;
        dg = 1.5f * sq;
    }
    gemm_body(gBuf[ia], gBuf[ib], gBuf[ic], al, dg);
}

// batched pair: z=0 -> C0 = A0*B0 ; z=1 -> C1 = A1*B1
__global__ void __launch_bounds__(256)
k_gemm_pair(int ia0, int ib0, int ic0, int ia1, int ib1, int ic1) {
    const float* A = gBuf[blockIdx.z ? ia1 : ia0];
    const float* B = gBuf[blockIdx.z ? ib1 : ib0];
    float*       C = gBuf[blockIdx.z ? ic1 : ic0];
    gemm_body(A, B, C, 1.0f, 0.0f);
}

// ---------------- outputs ----------------

__global__ void k_d(const float* __restrict__ x) {
    int idx = blockIdx.x * 256 + threadIdx.x;   // BBATCH*NN
    gD[idx] = x[idx & (NN - 1)] - x[idx];
}

// P_k[b] = d_b d_b^T + |P_u| + 0.01*Q^2
__global__ void k_out1(const float* __restrict__ Pu, const float* __restrict__ Qk,
                       float* __restrict__ out) {
    int idx = blockIdx.x * 256 + threadIdx.x;   // NN*NN
    int n = idx >> 10, m = idx & (NN - 1);
    float q = Qk[idx];
    float base = fabsf(Pu[idx]) + 0.01f * q * q;
    #pragma unroll
    for (int b = 0; b < BBATCH; b++)
        out[(size_t)b * NN * NN + idx] = base + gD[b * NN + n] * gD[b * NN + m];
}

// sigma^T[0,b,i,n] = x_b[n] +/- p[i,n];  p = av*v v^T + sqrt(c)*Y - (eps/2)*Z/sqrt(c)
__global__ void k_out2(const float* __restrict__ x, float* __restrict__ out,
                       int iy, int iz) {
    int idx = blockIdx.x * 256 + threadIdx.x;   // NN*NN, idx = i*NN+n
    int i = idx >> 10, n = idx & (NN - 1);
    float c   = gCval;
    float sqc = sqrtf(c);
    float s2e = sqrtf(2.0f * EPS);
    float av  = sqrtf((float)gLam) - (s2e - EPS / (2.0f * s2e));
    float pv  = av * (float)(gVd[i] * gVd[n])
              + sqc * gBuf[iy][idx]
              - (EPS * 0.5f / sqc) * gBuf[iz][idx];
    #pragma unroll
    for (int b = 0; b < BBATCH; b++) {
        float xb = x[b * NN + n];
        size_t base = (size_t)b * 2 * NN * NN;
        out[base + (size_t)i * NN + n]        = xb + pv;
        out[base + (size_t)(i + NN) * NN + n] = xb - pv;
    }
}

// ---------------- host ----------------

extern "C" void kernel_launch(void* const* d_in, const int* in_sizes, int n_in,
                              void* d_out, int out_size) {
    const float* x  = (const float*)d_in[0];   // [1,8,1024,1]
    const float* Pu = (const float*)d_in[1];   // [1024,1024]
    const float* Qk = (const float*)d_in[2];   // [1024,1024]
    float* out1 = (float*)d_out;               // P_k [8,1024,1024]
    float* out2 = out1 + (size_t)BBATCH * NN * NN;  // sigma^T [1,8,2048,1024]

    const int EW = NN * NN / 256;              // 4096 blocks
    dim3 gg(NN / 64, NN / 128);                // (16,8)
    dim3 gp(NN / 64, NN / 128, 2);

    // M = N*|P_u|
    k_buildM<<<EW, 256>>>(Pu);

    // Perron pair (fp64); all-ones start has ~0.999 overlap with Perron vector
    k_init_v1<<<1, NN>>>();
    for (int it = 0; it < 4; it++) {
        k_gemv64<<<NN / 8, 256>>>();
        k_norm64<<<1, NN>>>();
    }
    k_deflate<<<EW, 256>>>();

    // lambda_max(M') estimate (fp32); schedule carries margin for underestimate
    k_init_v2<<<1, NN>>>();
    for (int it = 0; it < 10; it++) {
        k_gemv32<<<NN / 8, 256>>>();
        k_norm32<<<1, NN>>>();
    }
    k_initY<<<EW, 256>>>();
    k_sched<<<1, 1>>>();

    // Scaled Newton-Schulz: Y->A^{1/2}, Z->A^{-1/2}
    // iter 1 (Z0 = I): G elementwise, Y1 = Y0*G, Z1 = G
    k_lin1<<<EW, 256>>>(3, 1);
    k_gemm<<<gg, 256>>>(1, 3, 4, 1.0f, 0.0f, -1);
    int Y = 4, Z = 3;
    int f0 = 0, f1 = 1, f2 = 2;
    for (int it = 2; it <= KNS; it++) {
        int G = f0;
        // G = sqrt(s)*(1.5I - 0.5*s*Z*Y)
        k_gemm<<<gg, 256>>>(Z, Y, G, 0.0f, 0.0f, it - 1);
        if (it < KNS) {
            int Yn = f1, Zn = f2;
            k_gemm_pair<<<gp, 256>>>(Y, G, Yn, G, Z, Zn);
            f0 = Y; f1 = Z; f2 = G;
            Y = Yn; Z = Zn;
        } else {
            int Yn = f1;
            k_gemm<<<gg, 256>>>(Y, G, Yn, 1.0f, 0.0f, -1);
            Y = Yn;                                   // Z stays Z_{K-1} (converged)
        }
    }

    // outputs
    k_d<<<BBATCH * NN / 256, 256>>>(x);
    k_out1<<<EW, 256>>>(Pu, Qk, out1);
    k_out2<<<EW, 256>>>(x, out2, Y, Z);
}

// round 11
// speedup vs baseline: 1.5745x; 1.1081x over previous
#include <cuda_runtime.h>
#include <math.h>

#define NN 1024
#define BBATCH 8
#define KNS 10
#define EPS 0.015f
#define CMARGIN 1.4f
#define PCTAS 128
#define PTHR 256

__device__ float  gBuf[6][NN * NN];
__device__ double gVd[NN];
__device__ double gLam;
__device__ float  gLmax;
__device__ float  gCval;
__device__ float  gS[KNS];
__device__ float  gD[BBATCH * NN];

// persistent power-iteration state
__device__ int    gBar64[16];
__device__ int    gBar32[24];
__device__ double gPartD[PCTAS];
__device__ float  gPartF[PCTAS];
__device__ double gInvD;
__device__ float  gInvF;
__device__ double gVa[NN], gVb[NN];
__device__ float  gFa[NN], gFb[NN];

// ---------------- global barrier (slot-per-use; slots zeroed each call) -----

__device__ __forceinline__ void gbar(int* slot) {
    __syncthreads();
    if (threadIdx.x == 0) {
        __threadfence();
        atomicAdd(slot, 1);
        volatile int* vs = (volatile int*)slot;
        while (*vs < PCTAS) { }
        __threadfence();
    }
    __syncthreads();
}

__global__ void k_barreset() {
    int t = threadIdx.x;
    if (t < 16) gBar64[t] = 0;
    if (t < 24) gBar32[t] = 0;
}

// ---------------- elementwise / small kernels ----------------

__global__ void k_buildM(const float* __restrict__ Pu) {
    int idx = blockIdx.x * 256 + threadIdx.x;
    gBuf[0][idx] = 1024.0f * fabsf(Pu[idx]);
}

// Fused fp64 Perron power iteration: 3 scaled applies + normalize + final apply.
// gVd = Perron vector (normalized), gLam = ||M v_hat|| ~ lambda1.
__global__ void __launch_bounds__(PTHR, 1) k_power64() {
    const int cta = blockIdx.x, tid = threadIdx.x;
    const int wid = tid >> 5, lane = tid & 31;
    const int row = cta * 8 + wid;
    int bi = 0;

    if (tid < 8) gVa[cta * 8 + tid] = 1.0 / 32.0;
    gbar(&gBar64[bi++]);

    // 3 applies with 1/512 rescale: a->b, b->a, a->b  (result in gVb)
    for (int t = 0; t < 3; t++) {
        const double* vin = (t & 1) ? gVb : gVa;
        double*       vout = (t & 1) ? gVa : gVb;
        const float* Arow = &gBuf[0][row * NN];
        double s = 0.0;
        #pragma unroll 8
        for (int j = lane; j < NN; j += 32) s += (double)Arow[j] * vin[j];
        #pragma unroll
        for (int o = 16; o; o >>= 1) s += __shfl_xor_sync(0xffffffffu, s, o);
        if (lane == 0) vout[row] = s * (1.0 / 512.0);
        gbar(&gBar64[bi++]);
    }

    // normalize gVb -> gVa
    if (tid == 0) {
        double p = 0.0;
        for (int i = 0; i < 8; i++) { double x = gVb[cta * 8 + i]; p += x * x; }
        gPartD[cta] = p;
    }
    gbar(&gBar64[bi++]);
    if (cta == 0 && tid == 0) {
        double S = 0.0;
        for (int i = 0; i < PCTAS; i++) S += gPartD[i];
        gInvD = 1.0 / sqrt(S);
    }
    gbar(&gBar64[bi++]);
    if (tid < 8) { int i = cta * 8 + tid; gVa[i] = gVb[i] * gInvD; }
    gbar(&gBar64[bi++]);

    // final apply (unscaled): gVb = M * v_hat
    {
        const float* Arow = &gBuf[0][row * NN];
        double s = 0.0;
        #pragma unroll 8
        for (int j = lane; j < NN; j += 32) s += (double)Arow[j] * gVa[j];
        #pragma unroll
        for (int o = 16; o; o >>= 1) s += __shfl_xor_sync(0xffffffffu, s, o);
        if (lane == 0) gVb[row] = s;
    }
    gbar(&gBar64[bi++]);
    if (tid == 0) {
        double p = 0.0;
        for (int i = 0; i < 8; i++) { double x = gVb[cta * 8 + i]; p += x * x; }
        gPartD[cta] = p;
    }
    gbar(&gBar64[bi++]);
    if (cta == 0 && tid == 0) {
        double S = 0.0;
        for (int i = 0; i < PCTAS; i++) S += gPartD[i];
        double nrm = sqrt(S);
        gLam = nrm;
        gInvD = 1.0 / nrm;
    }
    gbar(&gBar64[bi++]);
    if (tid < 8) { int i = cta * 8 + tid; gVd[i] = gVb[i] * gInvD; }
}

// M' = M - (lam1-eps) v v^T + eps*I  (in place on gBuf[0], fp64 math)
__global__ void k_deflate() {
    int idx = blockIdx.x * 256 + threadIdx.x;
    int n = idx >> 10, m = idx & (NN - 1);
    double val = (double)gBuf[0][idx] - (gLam - (double)EPS) * gVd[n] * gVd[m];
    if (n == m) val += (double)EPS;
    gBuf[0][idx] = (float)val;
}

// Fused fp32 power iteration on M': 9 scaled applies + normalize + final apply.
// gLmax = ||M' v_hat|| ~ lambda_max(M').
__global__ void __launch_bounds__(PTHR, 1) k_power32() {
    const int cta = blockIdx.x, tid = threadIdx.x;
    const int wid = tid >> 5, lane = tid & 31;
    const int row = cta * 8 + wid;
    int bi = 0;

    if (tid < 8) {
        unsigned i = (unsigned)(cta * 8 + tid);
        unsigned h = i * 2654435761u + 12345u;
        h ^= h >> 13; h *= 0x5bd1e995u; h ^= h >> 15;
        gFa[i] = (float)(h & 0xFFFFu) / 65536.0f - 0.5f;
    }
    gbar(&gBar32[bi++]);

    // 9 applies with 1/512 rescale: result alternates, ends in gFb (odd count)
    for (int t = 0; t < 9; t++) {
        const float* vin  = (t & 1) ? gFb : gFa;
        float*       vout = (t & 1) ? gFa : gFb;
        const float* Arow = &gBuf[0][row * NN];
        float s = 0.0f;
        #pragma unroll 8
        for (int j = lane; j < NN; j += 32) s += Arow[j] * vin[j];
        #pragma unroll
        for (int o = 16; o; o >>= 1) s += __shfl_xor_sync(0xffffffffu, s, o);
        if (lane == 0) vout[row] = s * (1.0f / 512.0f);
        gbar(&gBar32[bi++]);
    }

    // normalize gFb -> gFa
    if (tid == 0) {
        float p = 0.0f;
        for (int i = 0; i < 8; i++) { float x = gFb[cta * 8 + i]; p += x * x; }
        gPartF[cta] = p;
    }
    gbar(&gBar32[bi++]);
    if (cta == 0 && tid == 0) {
        float S = 0.0f;
        for (int i = 0; i < PCTAS; i++) S += gPartF[i];
        gInvF = 1.0f / sqrtf(S);
    }
    gbar(&gBar32[bi++]);
    if (tid < 8) { int i = cta * 8 + tid; gFa[i] = gFb[i] * gInvF; }
    gbar(&gBar32[bi++]);

    // final apply (unscaled): gFb = M' * v_hat ; gLmax = ||gFb||
    {
        const float* Arow = &gBuf[0][row * NN];
        float s = 0.0f;
        #pragma unroll 8
        for (int j = lane; j < NN; j += 32) s += Arow[j] * gFa[j];
        #pragma unroll
        for (int o = 16; o; o >>= 1) s += __shfl_xor_sync(0xffffffffu, s, o);
        if (lane == 0) gFb[row] = s;
    }
    gbar(&gBar32[bi++]);
    if (tid == 0) {
        float p = 0.0f;
        for (int i = 0; i < 8; i++) { float x = gFb[cta * 8 + i]; p += x * x; }
        gPartF[cta] = p;
    }
    gbar(&gBar32[bi++]);
    if (cta == 0 && tid == 0) {
        float S = 0.0f;
        for (int i = 0; i < PCTAS; i++) S += gPartF[i];
        gLmax = sqrtf(S);
    }
}

// Y0 = M'/c into gBuf[1]; store c
__global__ void k_initY() {
    int idx = blockIdx.x * 256 + threadIdx.x;
    float c = CMARGIN * gLmax;
    gBuf[1][idx] = gBuf[0][idx] / c;
    if (idx == 0) gCval = c;
}

// Optimal scaling schedule via single-thread bisection on f(w)=w(3-w)^2/4
__global__ void k_sched() {
    double a = 0.9 * (double)EPS / (double)gCval;
    double b = 0.80;
    for (int k = 0; k < KNS; k++) {
        double lo = 1.0 / b, hi = 2.9999 / b;
        for (int t = 0; t < 60; t++) {
            double s  = 0.5 * (lo + hi);
            double fa = s * a * (3.0 - s * a) * (3.0 - s * a) * 0.25;
            double fb = s * b * (3.0 - s * b) * (3.0 - s * b) * 0.25;
            if (fa < fb) lo = s; else hi = s;
        }
        double s = 0.5 * (lo + hi);
        gS[k] = (float)s;
        double sa = s * a, sb = s * b;
        double fa = sa * (3.0 - sa) * (3.0 - sa) * 0.25;
        double fb = sb * (3.0 - sb) * (3.0 - sb) * 0.25;
        a = fmin(fa, fb);
        b = (sa <= 1.0 && 1.0 <= sb) ? 1.0 : fmax(fa, fb);
        if (a > b) { double tmp = a; a = b; b = tmp; }
    }
}

// Iter-1 shortcut (Z0 = I): G = sqrt(s)*(1.5I - 0.5*s*Y0), elementwise
__global__ void k_lin1(int g, int y) {
    int idx = blockIdx.x * 256 + threadIdx.x;
    int n = idx >> 10, m = idx & (NN - 1);
    float s  = gS[0];
    float sq = sqrtf(s);
    gBuf[g][idx] = sq * (((n == m) ? 1.5f : 0.0f) - 0.5f * s * gBuf[y][idx]);
}

// ---------------- SGEMM: C = alpha*A*B + diag*I ----------------
// BM=128, BN=64, BK=16, 256 threads, 8x4 accum, global->reg prefetch.

__device__ __forceinline__ void gemm_body(const float* __restrict__ A,
                                          const float* __restrict__ B,
                                          float* __restrict__ C,
                                          float alpha, float diag)
{
    __shared__ float As[16][128];
    __shared__ float Bs[16][64];
    const int tid  = threadIdx.x;
    const int bm   = blockIdx.y << 7;
    const int bn   = blockIdx.x << 6;

    const int arow = tid >> 2;
    const int acol = (tid & 3) << 2;
    const int brow = tid >> 4;
    const int bcol = (tid & 15) << 2;
    const int ty   = tid >> 4;
    const int tx   = tid & 15;

    const float* Aptr = A + (bm + arow) * NN + acol;
    const float* Bptr = B + brow * NN + bn + bcol;

    float4 a0 = *(const float4*)(Aptr);
    float4 a1 = *(const float4*)(Aptr + 64 * NN);
    float4 b0 = *(const float4*)(Bptr);

    float acc[8][4];
    #pragma unroll
    for (int i = 0; i < 8; i++)
        #pragma unroll
        for (int j = 0; j < 4; j++) acc[i][j] = 0.0f;

    for (int kt = 0; kt < NN; kt += 16) {
        As[acol + 0][arow]      = a0.x;
        As[acol + 1][arow]      = a0.y;
        As[acol + 2][arow]      = a0.z;
        As[acol + 3][arow]      = a0.w;
        As[acol + 0][arow + 64] = a1.x;
        As[acol + 1][arow + 64] = a1.y;
        As[acol + 2][arow + 64] = a1.z;
        As[acol + 3][arow + 64] = a1.w;
        *(float4*)&Bs[brow][bcol] = b0;
        __syncthreads();

        if (kt + 16 < NN) {
            a0 = *(const float4*)(Aptr + kt + 16);
            a1 = *(const float4*)(Aptr + 64 * NN + kt + 16);
            b0 = *(const float4*)(Bptr + (kt + 16) * NN);
        }

        #pragma unroll
        for (int k = 0; k < 16; k++) {
            float af[8], bf[4];
            *(float4*)&af[0] = *(const float4*)&As[k][ty << 3];
            *(float4*)&af[4] = *(const float4*)&As[k][(ty << 3) + 4];
            *(float4*)&bf[0] = *(const float4*)&Bs[k][tx << 2];
            #pragma unroll
            for (int i = 0; i < 8; i++)
                #pragma unroll
                for (int j = 0; j < 4; j++)
                    acc[i][j] = fmaf(af[i], bf[j], acc[i][j]);
        }
        __syncthreads();
    }

    const int gc = bn + (tx << 2);
    #pragma unroll
    for (int i = 0; i < 8; i++) {
        int gr = bm + (ty << 3) + i;
        float4 o;
        o.x = alpha * acc[i][0] + ((gr == gc    ) ? diag : 0.0f);
        o.y = alpha * acc[i][1] + ((gr == gc + 1) ? diag : 0.0f);
        o.z = alpha * acc[i][2] + ((gr == gc + 2) ? diag : 0.0f);
        o.w = alpha * acc[i][3] + ((gr == gc + 3) ? diag : 0.0f);
        *(float4*)(C + (size_t)gr * NN + gc) = o;
    }
}

__global__ void __launch_bounds__(256)
k_gemm(int ia, int ib, int ic, float alpha, float diag, int sidx) {
    float al = alpha, dg = diag;
    if (sidx >= 0) {
        float s  = gS[sidx];
        float sq = sqrtf(s);
        al = -0.5f * s * sq;
        dg = 1.5f * sq;
    }
    gemm_body(gBuf[ia], gBuf[ib], gBuf[ic], al, dg);
}

__global__ void __launch_bounds__(256)
k_gemm_pair(int ia0, int ib0, int ic0, int ia1, int ib1, int ic1) {
    const float* A = gBuf[blockIdx.z ? ia1 : ia0];
    const float* B = gBuf[blockIdx.z ? ib1 : ib0];
    float*       C = gBuf[blockIdx.z ? ic1 : ic0];
    gemm_body(A, B, C, 1.0f, 0.0f);
}

// ---------------- outputs ----------------

__global__ void k_d(const float* __restrict__ x) {
    int idx = blockIdx.x * 256 + threadIdx.x;
    gD[idx] = x[idx & (NN - 1)] - x[idx];
}

__global__ void k_out1(const float* __restrict__ Pu, const float* __restrict__ Qk,
                       float* __restrict__ out) {
    int idx = blockIdx.x * 256 + threadIdx.x;
    int n = idx >> 10, m = idx & (NN - 1);
    float q = Qk[idx];
    float base = fabsf(Pu[idx]) + 0.01f * q * q;
    #pragma unroll
    for (int b = 0; b < BBATCH; b++)
        out[(size_t)b * NN * NN + idx] = base + gD[b * NN + n] * gD[b * NN + m];
}

__global__ void k_out2(const float* __restrict__ x, float* __restrict__ out,
                       int iy, int iz) {
    int idx = blockIdx.x * 256 + threadIdx.x;
    int i = idx >> 10, n = idx & (NN - 1);
    float c   = gCval;
    float sqc = sqrtf(c);
    float s2e = sqrtf(2.0f * EPS);
    float av  = sqrtf((float)gLam) - (s2e - EPS / (2.0f * s2e));
    float pv  = av * (float)(gVd[i] * gVd[n])
              + sqc * gBuf[iy][idx]
              - (EPS * 0.5f / sqc) * gBuf[iz][idx];
    #pragma unroll
    for (int b = 0; b < BBATCH; b++) {
        float xb = x[b * NN + n];
        size_t base = (size_t)b * 2 * NN * NN;
        out[base + (size_t)i * NN + n]        = xb + pv;
        out[base + (size_t)(i + NN) * NN + n] = xb - pv;
    }
}

// ---------------- host ----------------

extern "C" void kernel_launch(void* const* d_in, const int* in_sizes, int n_in,
                              void* d_out, int out_size) {
    const float* x  = (const float*)d_in[0];
    const float* Pu = (const float*)d_in[1];
    const float* Qk = (const float*)d_in[2];
    float* out1 = (float*)d_out;
    float* out2 = out1 + (size_t)BBATCH * NN * NN;

    const int EW = NN * NN / 256;
    dim3 gg(NN / 64, NN / 128);
    dim3 gp(NN / 64, NN / 128, 2);

    k_buildM<<<EW, 256>>>(Pu);

    // fused power iterations (barrier slots reset every call -> replay-safe)
    k_barreset<<<1, 32>>>();
    k_power64<<<PCTAS, PTHR>>>();
    k_deflate<<<EW, 256>>>();
    k_power32<<<PCTAS, PTHR>>>();
    k_initY<<<EW, 256>>>();
    k_sched<<<1, 1>>>();

    // Scaled Newton-Schulz: Y->A^{1/2}, Z->A^{-1/2}
    k_lin1<<<EW, 256>>>(3, 1);
    k_gemm<<<gg, 256>>>(1, 3, 4, 1.0f, 0.0f, -1);
    int Y = 4, Z = 3;
    int f0 = 0, f1 = 1, f2 = 2;
    for (int it = 2; it <= KNS; it++) {
        int G = f0;
        k_gemm<<<gg, 256>>>(Z, Y, G, 0.0f, 0.0f, it - 1);
        if (it < KNS) {
            int Yn = f1, Zn = f2;
            k_gemm_pair<<<gp, 256>>>(Y, G, Yn, G, Z, Zn);
            f0 = Y; f1 = Z; f2 = G;
            Y = Yn; Z = Zn;
        } else {
            int Yn = f1;
            k_gemm<<<gg, 256>>>(Y, G, Yn, 1.0f, 0.0f, -1);
            Y = Yn;
        }
    }

    k_d<<<BBATCH * NN / 256, 256>>>(x);
    k_out1<<<EW, 256>>>(Pu, Qk, out1);
    k_out2<<<EW, 256>>>(x, out2, Y, Z);
}

// round 12
// speedup vs baseline: 1.7588x; 1.1170x over previous
#include <cuda_runtime.h>
#include <math.h>

#define NN 1024
#define BBATCH 8
#define KNS 9
#define EPS 0.015f
#define CMARGIN 1.4f
#define PCTAS 128
#define PTHR 256

__device__ float  gBuf[6][NN * NN];
__device__ double gVd[NN];
__device__ double gLam;
__device__ float  gLmax;
__device__ float  gCval;
__device__ float  gS[KNS];

// persistent power-iteration state
__device__ int    gBar64[16];
__device__ int    gBar32[24];
__device__ double gPartD[PCTAS];
__device__ float  gPartF[PCTAS];
__device__ double gInvD;
__device__ float  gInvF;
__device__ double gVa[NN], gVb[NN];
__device__ float  gFa[NN], gFb[NN];

// ---------------- global barrier (slot-per-use; slots zeroed each call) -----

__device__ __forceinline__ void gbar(int* slot) {
    __syncthreads();
    if (threadIdx.x == 0) {
        __threadfence();
        atomicAdd(slot, 1);
        volatile int* vs = (volatile int*)slot;
        while (*vs < PCTAS) { }
        __threadfence();
    }
    __syncthreads();
}

__global__ void k_barreset() {
    int t = threadIdx.x;
    if (t < 16) gBar64[t] = 0;
    if (t < 24) gBar32[t] = 0;
}

// ---------------- elementwise / small kernels ----------------

__global__ void k_buildM(const float* __restrict__ Pu) {
    int idx = blockIdx.x * 256 + threadIdx.x;
    gBuf[0][idx] = 1024.0f * fabsf(Pu[idx]);
}

// Fused fp64 Perron power iteration: 3 scaled applies + normalize + final apply.
__global__ void __launch_bounds__(PTHR, 1) k_power64() {
    const int cta = blockIdx.x, tid = threadIdx.x;
    const int wid = tid >> 5, lane = tid & 31;
    const int row = cta * 8 + wid;
    int bi = 0;

    if (tid < 8) gVa[cta * 8 + tid] = 1.0 / 32.0;
    gbar(&gBar64[bi++]);

    for (int t = 0; t < 3; t++) {
        const double* vin = (t & 1) ? gVb : gVa;
        double*       vout = (t & 1) ? gVa : gVb;
        const float* Arow = &gBuf[0][row * NN];
        double s = 0.0;
        #pragma unroll 8
        for (int j = lane; j < NN; j += 32) s += (double)Arow[j] * vin[j];
        #pragma unroll
        for (int o = 16; o; o >>= 1) s += __shfl_xor_sync(0xffffffffu, s, o);
        if (lane == 0) vout[row] = s * (1.0 / 512.0);
        gbar(&gBar64[bi++]);
    }

    if (tid == 0) {
        double p = 0.0;
        for (int i = 0; i < 8; i++) { double x = gVb[cta * 8 + i]; p += x * x; }
        gPartD[cta] = p;
    }
    gbar(&gBar64[bi++]);
    if (cta == 0 && tid == 0) {
        double S = 0.0;
        for (int i = 0; i < PCTAS; i++) S += gPartD[i];
        gInvD = 1.0 / sqrt(S);
    }
    gbar(&gBar64[bi++]);
    if (tid < 8) { int i = cta * 8 + tid; gVa[i] = gVb[i] * gInvD; }
    gbar(&gBar64[bi++]);

    {
        const float* Arow = &gBuf[0][row * NN];
        double s = 0.0;
        #pragma unroll 8
        for (int j = lane; j < NN; j += 32) s += (double)Arow[j] * gVa[j];
        #pragma unroll
        for (int o = 16; o; o >>= 1) s += __shfl_xor_sync(0xffffffffu, s, o);
        if (lane == 0) gVb[row] = s;
    }
    gbar(&gBar64[bi++]);
    if (tid == 0) {
        double p = 0.0;
        for (int i = 0; i < 8; i++) { double x = gVb[cta * 8 + i]; p += x * x; }
        gPartD[cta] = p;
    }
    gbar(&gBar64[bi++]);
    if (cta == 0 && tid == 0) {
        double S = 0.0;
        for (int i = 0; i < PCTAS; i++) S += gPartD[i];
        double nrm = sqrt(S);
        gLam = nrm;
        gInvD = 1.0 / nrm;
    }
    gbar(&gBar64[bi++]);
    if (tid < 8) { int i = cta * 8 + tid; gVd[i] = gVb[i] * gInvD; }
}

// M' = M - (lam1-eps) v v^T + eps*I  (in place on gBuf[0], fp64 math)
__global__ void k_deflate() {
    int idx = blockIdx.x * 256 + threadIdx.x;
    int n = idx >> 10, m = idx & (NN - 1);
    double val = (double)gBuf[0][idx] - (gLam - (double)EPS) * gVd[n] * gVd[m];
    if (n == m) val += (double)EPS;
    gBuf[0][idx] = (float)val;
}

// Fused fp32 power iteration on M': 9 scaled applies + normalize + final apply.
__global__ void __launch_bounds__(PTHR, 1) k_power32() {
    const int cta = blockIdx.x, tid = threadIdx.x;
    const int wid = tid >> 5, lane = tid & 31;
    const int row = cta * 8 + wid;
    int bi = 0;

    if (tid < 8) {
        unsigned i = (unsigned)(cta * 8 + tid);
        unsigned h = i * 2654435761u + 12345u;
        h ^= h >> 13; h *= 0x5bd1e995u; h ^= h >> 15;
        gFa[i] = (float)(h & 0xFFFFu) / 65536.0f - 0.5f;
    }
    gbar(&gBar32[bi++]);

    for (int t = 0; t < 9; t++) {
        const float* vin  = (t & 1) ? gFb : gFa;
        float*       vout = (t & 1) ? gFa : gFb;
        const float* Arow = &gBuf[0][row * NN];
        float s = 0.0f;
        #pragma unroll 8
        for (int j = lane; j < NN; j += 32) s += Arow[j] * vin[j];
        #pragma unroll
        for (int o = 16; o; o >>= 1) s += __shfl_xor_sync(0xffffffffu, s, o);
        if (lane == 0) vout[row] = s * (1.0f / 512.0f);
        gbar(&gBar32[bi++]);
    }

    if (tid == 0) {
        float p = 0.0f;
        for (int i = 0; i < 8; i++) { float x = gFb[cta * 8 + i]; p += x * x; }
        gPartF[cta] = p;
    }
    gbar(&gBar32[bi++]);
    if (cta == 0 && tid == 0) {
        float S = 0.0f;
        for (int i = 0; i < PCTAS; i++) S += gPartF[i];
        gInvF = 1.0f / sqrtf(S);
    }
    gbar(&gBar32[bi++]);
    if (tid < 8) { int i = cta * 8 + tid; gFa[i] = gFb[i] * gInvF; }
    gbar(&gBar32[bi++]);

    {
        const float* Arow = &gBuf[0][row * NN];
        float s = 0.0f;
        #pragma unroll 8
        for (int j = lane; j < NN; j += 32) s += Arow[j] * gFa[j];
        #pragma unroll
        for (int o = 16; o; o >>= 1) s += __shfl_xor_sync(0xffffffffu, s, o);
        if (lane == 0) gFb[row] = s;
    }
    gbar(&gBar32[bi++]);
    if (tid == 0) {
        float p = 0.0f;
        for (int i = 0; i < 8; i++) { float x = gFb[cta * 8 + i]; p += x * x; }
        gPartF[cta] = p;
    }
    gbar(&gBar32[bi++]);
    if (cta == 0 && tid == 0) {
        float S = 0.0f;
        for (int i = 0; i < PCTAS; i++) S += gPartF[i];
        gLmax = sqrtf(S);
    }
}

// c = CMARGIN*lmax; then optimal scaling schedule via bisection on f(w)=w(3-w)^2/4
__global__ void k_sched() {
    float c = CMARGIN * gLmax;
    gCval = c;
    double a = 0.9 * (double)EPS / (double)c;
    double b = 0.80;
    for (int k = 0; k < KNS; k++) {
        double lo = 1.0 / b, hi = 2.9999 / b;
        for (int t = 0; t < 60; t++) {
            double s  = 0.5 * (lo + hi);
            double fa = s * a * (3.0 - s * a) * (3.0 - s * a) * 0.25;
            double fb = s * b * (3.0 - s * b) * (3.0 - s * b) * 0.25;
            if (fa < fb) lo = s; else hi = s;
        }
        double s = 0.5 * (lo + hi);
        gS[k] = (float)s;
        double sa = s * a, sb = s * b;
        double fa = sa * (3.0 - sa) * (3.0 - sa) * 0.25;
        double fb = sb * (3.0 - sb) * (3.0 - sb) * 0.25;
        a = fmin(fa, fb);
        b = (sa <= 1.0 && 1.0 <= sb) ? 1.0 : fmax(fa, fb);
        if (a > b) { double tmp = a; a = b; b = tmp; }
    }
}

// Iter-1 shortcut (Z0 = I, Y0 = M'/c implicit): G = sqrt(s)*(1.5I - 0.5*s*M'/c)
__global__ void k_lin1(int g) {
    int idx = blockIdx.x * 256 + threadIdx.x;
    int n = idx >> 10, m = idx & (NN - 1);
    float s  = gS[0];
    float sq = sqrtf(s);
    gBuf[g][idx] = sq * (((n == m) ? 1.5f : 0.0f) - 0.5f * s * gBuf[0][idx] / gCval);
}

// ---------------- SGEMM: C = alpha*A*B + diag*I ----------------

__device__ __forceinline__ void gemm_body(const float* __restrict__ A,
                                          const float* __restrict__ B,
                                          float* __restrict__ C,
                                          float alpha, float diag)
{
    __shared__ float As[16][128];
    __shared__ float Bs[16][64];
    const int tid  = threadIdx.x;
    const int bm   = blockIdx.y << 7;
    const int bn   = blockIdx.x << 6;

    const int arow = tid >> 2;
    const int acol = (tid & 3) << 2;
    const int brow = tid >> 4;
    const int bcol = (tid & 15) << 2;
    const int ty   = tid >> 4;
    const int tx   = tid & 15;

    const float* Aptr = A + (bm + arow) * NN + acol;
    const float* Bptr = B + brow * NN + bn + bcol;

    float4 a0 = *(const float4*)(Aptr);
    float4 a1 = *(const float4*)(Aptr + 64 * NN);
    float4 b0 = *(const float4*)(Bptr);

    float acc[8][4];
    #pragma unroll
    for (int i = 0; i < 8; i++)
        #pragma unroll
        for (int j = 0; j < 4; j++) acc[i][j] = 0.0f;

    for (int kt = 0; kt < NN; kt += 16) {
        As[acol + 0][arow]      = a0.x;
        As[acol + 1][arow]      = a0.y;
        As[acol + 2][arow]      = a0.z;
        As[acol + 3][arow]      = a0.w;
        As[acol + 0][arow + 64] = a1.x;
        As[acol + 1][arow + 64] = a1.y;
        As[acol + 2][arow + 64] = a1.z;
        As[acol + 3][arow + 64] = a1.w;
        *(float4*)&Bs[brow][bcol] = b0;
        __syncthreads();

        if (kt + 16 < NN) {
            a0 = *(const float4*)(Aptr + kt + 16);
            a1 = *(const float4*)(Aptr + 64 * NN + kt + 16);
            b0 = *(const float4*)(Bptr + (kt + 16) * NN);
        }

        #pragma unroll
        for (int k = 0; k < 16; k++) {
            float af[8], bf[4];
            *(float4*)&af[0] = *(const float4*)&As[k][ty << 3];
            *(float4*)&af[4] = *(const float4*)&As[k][(ty << 3) + 4];
            *(float4*)&bf[0] = *(const float4*)&Bs[k][tx << 2];
            #pragma unroll
            for (int i = 0; i < 8; i++)
                #pragma unroll
                for (int j = 0; j < 4; j++)
                    acc[i][j] = fmaf(af[i], bf[j], acc[i][j]);
        }
        __syncthreads();
    }

    const int gc = bn + (tx << 2);
    #pragma unroll
    for (int i = 0; i < 8; i++) {
        int gr = bm + (ty << 3) + i;
        float4 o;
        o.x = alpha * acc[i][0] + ((gr == gc    ) ? diag : 0.0f);
        o.y = alpha * acc[i][1] + ((gr == gc + 1) ? diag : 0.0f);
        o.z = alpha * acc[i][2] + ((gr == gc + 2) ? diag : 0.0f);
        o.w = alpha * acc[i][3] + ((gr == gc + 3) ? diag : 0.0f);
        *(float4*)(C + (size_t)gr * NN + gc) = o;
    }
}

// sidx >= 0: alpha=-0.5*s^1.5, diag=1.5*sqrt(s); sidx==-2: alpha=1/c, diag=0
__global__ void __launch_bounds__(256)
k_gemm(int ia, int ib, int ic, float alpha, float diag, int sidx) {
    float al = alpha, dg = diag;
    if (sidx >= 0) {
        float s  = gS[sidx];
        float sq = sqrtf(s);
        al = -0.5f * s * sq;
        dg = 1.5f * sq;
    } else if (sidx == -2) {
        al = 1.0f / gCval;
        dg = 0.0f;
    }
    gemm_body(gBuf[ia], gBuf[ib], gBuf[ic], al, dg);
}

__global__ void __launch_bounds__(256)
k_gemm_pair(int ia0, int ib0, int ic0, int ia1, int ib1, int ic1) {
    const float* A = gBuf[blockIdx.z ? ia1 : ia0];
    const float* B = gBuf[blockIdx.z ? ib1 : ib0];
    float*       C = gBuf[blockIdx.z ? ic1 : ic0];
    gemm_body(A, B, C, 1.0f, 0.0f);
}

// ---------------- outputs ----------------

// P_k[b] = d_b d_b^T + |P_u| + 0.01*Q^2, d_b[n] = x[n] - x[b*NN+n] (inline)
__global__ void k_out1(const float* __restrict__ x,
                       const float* __restrict__ Pu, const float* __restrict__ Qk,
                       float* __restrict__ out) {
    int idx = blockIdx.x * 256 + threadIdx.x;
    int n = idx >> 10, m = idx & (NN - 1);
    float q = Qk[idx];
    float base = fabsf(Pu[idx]) + 0.01f * q * q;
    float x0n = x[n], x0m = x[m];
    #pragma unroll
    for (int b = 0; b < BBATCH; b++) {
        float dn = x0n - x[b * NN + n];
        float dm = x0m - x[b * NN + m];
        out[(size_t)b * NN * NN + idx] = base + dn * dm;
    }
}

// sigma^T[0,b,i,n] = x_b[n] +/- p[i,n];  p = av*v v^T + sqrt(c)*Y - (eps/2)*Z/sqrt(c)
__global__ void k_out2(const float* __restrict__ x, float* __restrict__ out,
                       int iy, int iz) {
    int idx = blockIdx.x * 256 + threadIdx.x;
    int i = idx >> 10, n = idx & (NN - 1);
    float c   = gCval;
    float sqc = sqrtf(c);
    float s2e = sqrtf(2.0f * EPS);
    float av  = sqrtf((float)gLam) - (s2e - EPS / (2.0f * s2e));
    float pv  = av * (float)(gVd[i] * gVd[n])
              + sqc * gBuf[iy][idx]
              - (EPS * 0.5f / sqc) * gBuf[iz][idx];
    #pragma unroll
    for (int b = 0; b < BBATCH; b++) {
        float xb = x[b * NN + n];
        size_t base = (size_t)b * 2 * NN * NN;
        out[base + (size_t)i * NN + n]        = xb + pv;
        out[base + (size_t)(i + NN) * NN + n] = xb - pv;
    }
}

// ---------------- host ----------------

extern "C" void kernel_launch(void* const* d_in, const int* in_sizes, int n_in,
                              void* d_out, int out_size) {
    const float* x  = (const float*)d_in[0];
    const float* Pu = (const float*)d_in[1];
    const float* Qk = (const float*)d_in[2];
    float* out1 = (float*)d_out;
    float* out2 = out1 + (size_t)BBATCH * NN * NN;

    const int EW = NN * NN / 256;
    dim3 gg(NN / 64, NN / 128);
    dim3 gp(NN / 64, NN / 128, 2);

    k_buildM<<<EW, 256>>>(Pu);

    k_barreset<<<1, 32>>>();
    k_power64<<<PCTAS, PTHR>>>();
    k_deflate<<<EW, 256>>>();
    k_power32<<<PCTAS, PTHR>>>();
    k_sched<<<1, 1>>>();

    // Scaled Newton-Schulz; iter 1: G1 elementwise, Y1 = (M'/c)*G1 via alpha=1/c
    k_lin1<<<EW, 256>>>(3);
    k_gemm<<<gg, 256>>>(0, 3, 4, 0.0f, 0.0f, -2);
    int Y = 4, Z = 3;
    int f0 = 0, f1 = 1, f2 = 2;
    for (int it = 2; it <= KNS; it++) {
        int G = f0;
        k_gemm<<<gg, 256>>>(Z, Y, G, 0.0f, 0.0f, it - 1);
        if (it < KNS) {
            int Yn = f1, Zn = f2;
            k_gemm_pair<<<gp, 256>>>(Y, G, Yn, G, Z, Zn);
            f0 = Y; f1 = Z; f2 = G;
            Y = Yn; Z = Zn;
        } else {
            int Yn = f1;
            k_gemm<<<gg, 256>>>(Y, G, Yn, 1.0f, 0.0f, -1);
            Y = Yn;
        }
    }

    k_out1<<<EW, 256>>>(x, Pu, Qk, out1);
    k_out2<<<EW, 256>>>(x, out2, Y, Z);
}

// round 13
// speedup vs baseline: 1.9816x; 1.1266x over previous
#include <cuda_runtime.h>
#include <math.h>

#define NN 1024
#define BBATCH 8
#define KNS 8
#define EPS 0.015f
#define CMARGIN 1.4f
#define PCTAS 128
#define PTHR 256

__device__ float  gBuf[6][NN * NN];
__device__ double gVd[NN];
__device__ double gLam;
__device__ float  gLmax;
__device__ float  gCval;
__device__ float  gS[KNS];

// persistent power-iteration state
__device__ int    gBar64[16];
__device__ int    gBar32[24];
__device__ double gPartD[PCTAS];
__device__ float  gPartF[PCTAS];
__device__ double gInvD;
__device__ float  gInvF;
__device__ double gVa[NN], gVb[NN];
__device__ float  gFa[NN], gFb[NN];

// ---------------- global barrier (slot-per-use; slots zeroed each call) -----

__device__ __forceinline__ void gbar(int* slot) {
    __syncthreads();
    if (threadIdx.x == 0) {
        __threadfence();
        atomicAdd(slot, 1);
        volatile int* vs = (volatile int*)slot;
        while (*vs < PCTAS) { }
        __threadfence();
    }
    __syncthreads();
}

__global__ void k_barreset() {
    int t = threadIdx.x;
    if (t < 16) gBar64[t] = 0;
    if (t < 24) gBar32[t] = 0;
}

// Fused fp64 Perron power iteration on M = 1024*|Pu| (read inline from Pu).
// 3 rescaled applies + normalize + final apply; gLam = ||M v_hat|| ~ lambda1.
__global__ void __launch_bounds__(PTHR, 1) k_power64(const float* __restrict__ Pu) {
    const int cta = blockIdx.x, tid = threadIdx.x;
    const int wid = tid >> 5, lane = tid & 31;
    const int row = cta * 8 + wid;
    int bi = 0;

    if (tid < 8) gVa[cta * 8 + tid] = 1.0 / 32.0;
    gbar(&gBar64[bi++]);

    // 3 applies: vout = (1024*|Pu|)*vin / 512 = 2 * |Pu|*vin
    for (int t = 0; t < 3; t++) {
        const double* vin = (t & 1) ? gVb : gVa;
        double*       vout = (t & 1) ? gVa : gVb;
        const float* Arow = Pu + (size_t)row * NN;
        double s = 0.0;
        #pragma unroll 8
        for (int j = lane; j < NN; j += 32) s += (double)fabsf(Arow[j]) * vin[j];
        #pragma unroll
        for (int o = 16; o; o >>= 1) s += __shfl_xor_sync(0xffffffffu, s, o);
        if (lane == 0) vout[row] = s * 2.0;
        gbar(&gBar64[bi++]);
    }

    if (tid == 0) {
        double p = 0.0;
        for (int i = 0; i < 8; i++) { double x = gVb[cta * 8 + i]; p += x * x; }
        gPartD[cta] = p;
    }
    gbar(&gBar64[bi++]);
    if (cta == 0 && tid == 0) {
        double S = 0.0;
        for (int i = 0; i < PCTAS; i++) S += gPartD[i];
        gInvD = 1.0 / sqrt(S);
    }
    gbar(&gBar64[bi++]);
    if (tid < 8) { int i = cta * 8 + tid; gVa[i] = gVb[i] * gInvD; }
    gbar(&gBar64[bi++]);

    // final apply (unscaled): gVb = 1024*|Pu| * v_hat
    {
        const float* Arow = Pu + (size_t)row * NN;
        double s = 0.0;
        #pragma unroll 8
        for (int j = lane; j < NN; j += 32) s += (double)fabsf(Arow[j]) * gVa[j];
        #pragma unroll
        for (int o = 16; o; o >>= 1) s += __shfl_xor_sync(0xffffffffu, s, o);
        if (lane == 0) gVb[row] = s * 1024.0;
    }
    gbar(&gBar64[bi++]);
    if (tid == 0) {
        double p = 0.0;
        for (int i = 0; i < 8; i++) { double x = gVb[cta * 8 + i]; p += x * x; }
        gPartD[cta] = p;
    }
    gbar(&gBar64[bi++]);
    if (cta == 0 && tid == 0) {
        double S = 0.0;
        for (int i = 0; i < PCTAS; i++) S += gPartD[i];
        double nrm = sqrt(S);
        gLam = nrm;
        gInvD = 1.0 / nrm;
    }
    gbar(&gBar64[bi++]);
    if (tid < 8) { int i = cta * 8 + tid; gVd[i] = gVb[i] * gInvD; }
}

// M' = 1024*|Pu| - (lam1-eps) v v^T + eps*I  -> gBuf[0] (fp64 math)
__global__ void k_deflate(const float* __restrict__ Pu) {
    int idx = blockIdx.x * 256 + threadIdx.x;
    int n = idx >> 10, m = idx & (NN - 1);
    double val = 1024.0 * (double)fabsf(Pu[idx])
               - (gLam - (double)EPS) * gVd[n] * gVd[m];
    if (n == m) val += (double)EPS;
    gBuf[0][idx] = (float)val;
}

// Fused fp32 power iteration on M' + schedule computation in the cta0 tail.
__global__ void __launch_bounds__(PTHR, 1) k_power32() {
    const int cta = blockIdx.x, tid = threadIdx.x;
    const int wid = tid >> 5, lane = tid & 31;
    const int row = cta * 8 + wid;
    int bi = 0;

    if (tid < 8) {
        unsigned i = (unsigned)(cta * 8 + tid);
        unsigned h = i * 2654435761u + 12345u;
        h ^= h >> 13; h *= 0x5bd1e995u; h ^= h >> 15;
        gFa[i] = (float)(h & 0xFFFFu) / 65536.0f - 0.5f;
    }
    gbar(&gBar32[bi++]);

    for (int t = 0; t < 9; t++) {
        const float* vin  = (t & 1) ? gFb : gFa;
        float*       vout = (t & 1) ? gFa : gFb;
        const float* Arow = &gBuf[0][row * NN];
        float s = 0.0f;
        #pragma unroll 8
        for (int j = lane; j < NN; j += 32) s += Arow[j] * vin[j];
        #pragma unroll
        for (int o = 16; o; o >>= 1) s += __shfl_xor_sync(0xffffffffu, s, o);
        if (lane == 0) vout[row] = s * (1.0f / 512.0f);
        gbar(&gBar32[bi++]);
    }

    if (tid == 0) {
        float p = 0.0f;
        for (int i = 0; i < 8; i++) { float x = gFb[cta * 8 + i]; p += x * x; }
        gPartF[cta] = p;
    }
    gbar(&gBar32[bi++]);
    if (cta == 0 && tid == 0) {
        float S = 0.0f;
        for (int i = 0; i < PCTAS; i++) S += gPartF[i];
        gInvF = 1.0f / sqrtf(S);
    }
    gbar(&gBar32[bi++]);
    if (tid < 8) { int i = cta * 8 + tid; gFa[i] = gFb[i] * gInvF; }
    gbar(&gBar32[bi++]);

    {
        const float* Arow = &gBuf[0][row * NN];
        float s = 0.0f;
        #pragma unroll 8
        for (int j = lane; j < NN; j += 32) s += Arow[j] * gFa[j];
        #pragma unroll
        for (int o = 16; o; o >>= 1) s += __shfl_xor_sync(0xffffffffu, s, o);
        if (lane == 0) gFb[row] = s;
    }
    gbar(&gBar32[bi++]);
    if (tid == 0) {
        float p = 0.0f;
        for (int i = 0; i < 8; i++) { float x = gFb[cta * 8 + i]; p += x * x; }
        gPartF[cta] = p;
    }
    gbar(&gBar32[bi++]);
    if (cta == 0 && tid == 0) {
        float S = 0.0f;
        for (int i = 0; i < PCTAS; i++) S += gPartF[i];
        float lmax = sqrtf(S);
        gLmax = lmax;
        // ---- scaling schedule (folded k_sched) ----
        float c = CMARGIN * lmax;
        gCval = c;
        double a = 0.9 * (double)EPS / (double)c;
        double b = 0.80;
        for (int k = 0; k < KNS; k++) {
            double lo = 1.0 / b, hi = 2.9999 / b;
            for (int t = 0; t < 60; t++) {
                double s  = 0.5 * (lo + hi);
                double fa = s * a * (3.0 - s * a) * (3.0 - s * a) * 0.25;
                double fb = s * b * (3.0 - s * b) * (3.0 - s * b) * 0.25;
                if (fa < fb) lo = s; else hi = s;
            }
            double s = 0.5 * (lo + hi);
            gS[k] = (float)s;
            double sa = s * a, sb = s * b;
            double fa = sa * (3.0 - sa) * (3.0 - sa) * 0.25;
            double fb = sb * (3.0 - sb) * (3.0 - sb) * 0.25;
            a = fmin(fa, fb);
            b = (sa <= 1.0 && 1.0 <= sb) ? 1.0 : fmax(fa, fb);
            if (a > b) { double tmp = a; a = b; b = tmp; }
        }
    }
}

// Iter-1 shortcut (Z0 = I, Y0 = M'/c implicit): G = sqrt(s)*(1.5I - 0.5*s*M'/c)
__global__ void k_lin1(int g) {
    int idx = blockIdx.x * 256 + threadIdx.x;
    int n = idx >> 10, m = idx & (NN - 1);
    float s  = gS[0];
    float sq = sqrtf(s);
    gBuf[g][idx] = sq * (((n == m) ? 1.5f : 0.0f) - 0.5f * s * gBuf[0][idx] / gCval);
}

// ---------------- SGEMM: C = alpha*A*B + diag*I ----------------

__device__ __forceinline__ void gemm_body(const float* __restrict__ A,
                                          const float* __restrict__ B,
                                          float* __restrict__ C,
                                          float alpha, float diag)
{
    __shared__ float As[16][128];
    __shared__ float Bs[16][64];
    const int tid  = threadIdx.x;
    const int bm   = blockIdx.y << 7;
    const int bn   = blockIdx.x << 6;

    const int arow = tid >> 2;
    const int acol = (tid & 3) << 2;
    const int brow = tid >> 4;
    const int bcol = (tid & 15) << 2;
    const int ty   = tid >> 4;
    const int tx   = tid & 15;

    const float* Aptr = A + (bm + arow) * NN + acol;
    const float* Bptr = B + brow * NN + bn + bcol;

    float4 a0 = *(const float4*)(Aptr);
    float4 a1 = *(const float4*)(Aptr + 64 * NN);
    float4 b0 = *(const float4*)(Bptr);

    float acc[8][4];
    #pragma unroll
    for (int i = 0; i < 8; i++)
        #pragma unroll
        for (int j = 0; j < 4; j++) acc[i][j] = 0.0f;

    for (int kt = 0; kt < NN; kt += 16) {
        As[acol + 0][arow]      = a0.x;
        As[acol + 1][arow]      = a0.y;
        As[acol + 2][arow]      = a0.z;
        As[acol + 3][arow]      = a0.w;
        As[acol + 0][arow + 64] = a1.x;
        As[acol + 1][arow + 64] = a1.y;
        As[acol + 2][arow + 64] = a1.z;
        As[acol + 3][arow + 64] = a1.w;
        *(float4*)&Bs[brow][bcol] = b0;
        __syncthreads();

        if (kt + 16 < NN) {
            a0 = *(const float4*)(Aptr + kt + 16);
            a1 = *(const float4*)(Aptr + 64 * NN + kt + 16);
            b0 = *(const float4*)(Bptr + (kt + 16) * NN);
        }

        #pragma unroll
        for (int k = 0; k < 16; k++) {
            float af[8], bf[4];
            *(float4*)&af[0] = *(const float4*)&As[k][ty << 3];
            *(float4*)&af[4] = *(const float4*)&As[k][(ty << 3) + 4];
            *(float4*)&bf[0] = *(const float4*)&Bs[k][tx << 2];
            #pragma unroll
            for (int i = 0; i < 8; i++)
                #pragma unroll
                for (int j = 0; j < 4; j++)
                    acc[i][j] = fmaf(af[i], bf[j], acc[i][j]);
        }
        __syncthreads();
    }

    const int gc = bn + (tx << 2);
    #pragma unroll
    for (int i = 0; i < 8; i++) {
        int gr = bm + (ty << 3) + i;
        float4 o;
        o.x = alpha * acc[i][0] + ((gr == gc    ) ? diag : 0.0f);
        o.y = alpha * acc[i][1] + ((gr == gc + 1) ? diag : 0.0f);
        o.z = alpha * acc[i][2] + ((gr == gc + 2) ? diag : 0.0f);
        o.w = alpha * acc[i][3] + ((gr == gc + 3) ? diag : 0.0f);
        *(float4*)(C + (size_t)gr * NN + gc) = o;
    }
}

// sidx >= 0: alpha=-0.5*s^1.5, diag=1.5*sqrt(s); sidx==-2: alpha=1/c, diag=0
__global__ void __launch_bounds__(256)
k_gemm(int ia, int ib, int ic, float alpha, float diag, int sidx) {
    float al = alpha, dg = diag;
    if (sidx >= 0) {
        float s  = gS[sidx];
        float sq = sqrtf(s);
        al = -0.5f * s * sq;
        dg = 1.5f * sq;
    } else if (sidx == -2) {
        al = 1.0f / gCval;
        dg = 0.0f;
    }
    gemm_body(gBuf[ia], gBuf[ib], gBuf[ic], al, dg);
}

__global__ void __launch_bounds__(256)
k_gemm_pair(int ia0, int ib0, int ic0, int ia1, int ib1, int ic1) {
    const float* A = gBuf[blockIdx.z ? ia1 : ia0];
    const float* B = gBuf[blockIdx.z ? ib1 : ib0];
    float*       C = gBuf[blockIdx.z ? ic1 : ic0];
    gemm_body(A, B, C, 1.0f, 0.0f);
}

// ---------------- outputs ----------------

// P_k[b] = d_b d_b^T + |P_u| + 0.01*Q^2, d_b[n] = x[n] - x[b*NN+n]
__global__ void k_out1(const float* __restrict__ x,
                       const float* __restrict__ Pu, const float* __restrict__ Qk,
                       float* __restrict__ out) {
    int idx = blockIdx.x * 256 + threadIdx.x;
    int n = idx >> 10, m = idx & (NN - 1);
    float q = Qk[idx];
    float base = fabsf(Pu[idx]) + 0.01f * q * q;
    float x0n = x[n], x0m = x[m];
    #pragma unroll
    for (int b = 0; b < BBATCH; b++) {
        float dn = x0n - x[b * NN + n];
        float dm = x0m - x[b * NN + m];
        out[(size_t)b * NN * NN + idx] = base + dn * dm;
    }
}

// sigma^T[0,b,i,n] = x_b[n] +/- p[i,n];  p = av*v v^T + sqrt(c)*Y - (eps/2)*Z/sqrt(c)
__global__ void k_out2(const float* __restrict__ x, float* __restrict__ out,
                       int iy, int iz) {
    int idx = blockIdx.x * 256 + threadIdx.x;
    int i = idx >> 10, n = idx & (NN - 1);
    float c   = gCval;
    float sqc = sqrtf(c);
    float s2e = sqrtf(2.0f * EPS);
    float av  = sqrtf((float)gLam) - (s2e - EPS / (2.0f * s2e));
    float pv  = av * (float)(gVd[i] * gVd[n])
              + sqc * gBuf[iy][idx]
              - (EPS * 0.5f / sqc) * gBuf[iz][idx];
    #pragma unroll
    for (int b = 0; b < BBATCH; b++) {
        float xb = x[b * NN + n];
        size_t base = (size_t)b * 2 * NN * NN;
        out[base + (size_t)i * NN + n]        = xb + pv;
        out[base + (size_t)(i + NN) * NN + n] = xb - pv;
    }
}

// ---------------- host ----------------

extern "C" void kernel_launch(void* const* d_in, const int* in_sizes, int n_in,
                              void* d_out, int out_size) {
    const float* x  = (const float*)d_in[0];
    const float* Pu = (const float*)d_in[1];
    const float* Qk = (const float*)d_in[2];
    float* out1 = (float*)d_out;
    float* out2 = out1 + (size_t)BBATCH * NN * NN;

    const int EW = NN * NN / 256;
    dim3 gg(NN / 64, NN / 128);
    dim3 gp(NN / 64, NN / 128, 2);

    k_barreset<<<1, 32>>>();
    k_power64<<<PCTAS, PTHR>>>(Pu);
    k_deflate<<<EW, 256>>>(Pu);
    k_power32<<<PCTAS, PTHR>>>();   // includes schedule computation

    // Scaled Newton-Schulz; iter 1: G1 elementwise, Y1 = (M'/c)*G1 via alpha=1/c
    k_lin1<<<EW, 256>>>(3);
    k_gemm<<<gg, 256>>>(0, 3, 4, 0.0f, 0.0f, -2);
    int Y = 4, Z = 3;
    int f0 = 0, f1 = 1, f2 = 2;
    for (int it = 2; it <= KNS; it++) {
        int G = f0;
        k_gemm<<<gg, 256>>>(Z, Y, G, 0.0f, 0.0f, it - 1);
        if (it < KNS) {
            int Yn = f1, Zn = f2;
            k_gemm_pair<<<gp, 256>>>(Y, G, Yn, G, Z, Zn);
            f0 = Y; f1 = Z; f2 = G;
            Y = Yn; Z = Zn;
        } else {
            int Yn = f1;
            k_gemm<<<gg, 256>>>(Y, G, Yn, 1.0f, 0.0f, -1);
            Y = Yn;
        }
    }

    k_out1<<<EW, 256>>>(x, Pu, Qk, out1);
    k_out2<<<EW, 256>>>(x, out2, Y, Z);
}

// round 15
// speedup vs baseline: 2.1144x; 1.0670x over previous
#include <cuda_runtime.h>
#include <math.h>

#define NN 1024
#define BBATCH 8
#define KNS 8
#define EPS 0.015f
#define CMARGIN 1.4f
#define PCTAS 128
#define PTHR 256

__device__ float  gBuf[6][NN * NN];
__device__ double gVd[NN];
__device__ double gLam;
__device__ float  gLmax;
__device__ float  gCval;
__device__ float  gS[KNS];

// persistent power-iteration state
__device__ int    gBar64[16];
__device__ int    gBar32[24];
__device__ double gPartD[PCTAS];
__device__ float  gPartF[PCTAS];
__device__ double gInvD;
__device__ float  gInvF;
__device__ double gVa[NN], gVb[NN];
__device__ float  gFa[NN], gFb[NN];

// ---------------- global barrier (slot-per-use; slots zeroed each call) -----

__device__ __forceinline__ void gbar(int* slot) {
    __syncthreads();
    if (threadIdx.x == 0) {
        __threadfence();
        atomicAdd(slot, 1);
        volatile int* vs = (volatile int*)slot;
        while (*vs < PCTAS) { __nanosleep(64); }
        __threadfence();
    }
    __syncthreads();
}

__global__ void k_barreset() {
    int t = threadIdx.x;
    if (t < 16) gBar64[t] = 0;
    if (t < 24) gBar32[t] = 0;
}

// Fused fp64 Perron power iteration on M = 1024*|Pu| (read inline from Pu).
// 3 rescaled applies + normalize + final apply; gLam = ||M v_hat|| ~ lambda1.
__global__ void __launch_bounds__(PTHR, 1) k_power64(const float* __restrict__ Pu) {
    const int cta = blockIdx.x, tid = threadIdx.x;
    const int wid = tid >> 5, lane = tid & 31;
    const int row = cta * 8 + wid;
    int bi = 0;

    if (tid < 8) gVa[cta * 8 + tid] = 1.0 / 32.0;
    gbar(&gBar64[bi++]);

    // 3 applies: vout = (1024*|Pu|)*vin / 512 = 2 * |Pu|*vin
    for (int t = 0; t < 3; t++) {
        const double* vin = (t & 1) ? gVb : gVa;
        double*       vout = (t & 1) ? gVa : gVb;
        const float* Arow = Pu + (size_t)row * NN;
        double s = 0.0;
        #pragma unroll 8
        for (int j = lane; j < NN; j += 32) s += (double)fabsf(Arow[j]) * vin[j];
        #pragma unroll
        for (int o = 16; o; o >>= 1) s += __shfl_xor_sync(0xffffffffu, s, o);
        if (lane == 0) vout[row] = s * 2.0;
        gbar(&gBar64[bi++]);
    }

    if (tid == 0) {
        double p = 0.0;
        for (int i = 0; i < 8; i++) { double x = gVb[cta * 8 + i]; p += x * x; }
        gPartD[cta] = p;
    }
    gbar(&gBar64[bi++]);
    if (cta == 0 && tid == 0) {
        double S = 0.0;
        for (int i = 0; i < PCTAS; i++) S += gPartD[i];
        gInvD = 1.0 / sqrt(S);
    }
    gbar(&gBar64[bi++]);
    if (tid < 8) { int i = cta * 8 + tid; gVa[i] = gVb[i] * gInvD; }
    gbar(&gBar64[bi++]);

    // final apply (unscaled): gVb = 1024*|Pu| * v_hat
    {
        const float* Arow = Pu + (size_t)row * NN;
        double s = 0.0;
        #pragma unroll 8
        for (int j = lane; j < NN; j += 32) s += (double)fabsf(Arow[j]) * gVa[j];
        #pragma unroll
        for (int o = 16; o; o >>= 1) s += __shfl_xor_sync(0xffffffffu, s, o);
        if (lane == 0) gVb[row] = s * 1024.0;
    }
    gbar(&gBar64[bi++]);
    if (tid == 0) {
        double p = 0.0;
        for (int i = 0; i < 8; i++) { double x = gVb[cta * 8 + i]; p += x * x; }
        gPartD[cta] = p;
    }
    gbar(&gBar64[bi++]);
    if (cta == 0 && tid == 0) {
        double S = 0.0;
        for (int i = 0; i < PCTAS; i++) S += gPartD[i];
        double nrm = sqrt(S);
        gLam = nrm;
        gInvD = 1.0 / nrm;
    }
    gbar(&gBar64[bi++]);
    if (tid < 8) { int i = cta * 8 + tid; gVd[i] = gVb[i] * gInvD; }
}

// Fused: deflation (M' rows written by the CTA that reuses them) + fp32 power
// iteration on M' + scaling-schedule computation in the cta0 tail.
__global__ void __launch_bounds__(PTHR, 1) k_power32(const float* __restrict__ Pu) {
    const int cta = blockIdx.x, tid = threadIdx.x;
    const int wid = tid >> 5, lane = tid & 31;
    const int row = cta * 8 + wid;
    int bi = 0;

    // prologue: M' = 1024*|Pu| - (lam1-eps) v v^T + eps*I  for this CTA's 8 rows
    {
        const double lam = gLam - (double)EPS;
        const int base = cta * 8192;                 // 8 rows * 1024
        #pragma unroll 4
        for (int t = tid; t < 8192; t += PTHR) {
            int idx = base + t;
            int n = idx >> 10, m = idx & (NN - 1);
            double val = 1024.0 * (double)fabsf(Pu[idx]) - lam * gVd[n] * gVd[m];
            if (n == m) val += (double)EPS;
            gBuf[0][idx] = (float)val;
        }
        if (tid < 8) {
            unsigned i = (unsigned)(cta * 8 + tid);
            unsigned h = i * 2654435761u + 12345u;
            h ^= h >> 13; h *= 0x5bd1e995u; h ^= h >> 15;
            gFa[i] = (float)(h & 0xFFFFu) / 65536.0f - 0.5f;
        }
    }
    gbar(&gBar32[bi++]);

    for (int t = 0; t < 9; t++) {
        const float* vin  = (t & 1) ? gFb : gFa;
        float*       vout = (t & 1) ? gFa : gFb;
        const float* Arow = &gBuf[0][row * NN];
        float s = 0.0f;
        #pragma unroll 8
        for (int j = lane; j < NN; j += 32) s += Arow[j] * vin[j];
        #pragma unroll
        for (int o = 16; o; o >>= 1) s += __shfl_xor_sync(0xffffffffu, s, o);
        if (lane == 0) vout[row] = s * (1.0f / 512.0f);
        gbar(&gBar32[bi++]);
    }

    if (tid == 0) {
        float p = 0.0f;
        for (int i = 0; i < 8; i++) { float x = gFb[cta * 8 + i]; p += x * x; }
        gPartF[cta] = p;
    }
    gbar(&gBar32[bi++]);
    if (cta == 0 && tid == 0) {
        float S = 0.0f;
        for (int i = 0; i < PCTAS; i++) S += gPartF[i];
        gInvF = 1.0f / sqrtf(S);
    }
    gbar(&gBar32[bi++]);
    if (tid < 8) { int i = cta * 8 + tid; gFa[i] = gFb[i] * gInvF; }
    gbar(&gBar32[bi++]);

    {
        const float* Arow = &gBuf[0][row * NN];
        float s = 0.0f;
        #pragma unroll 8
        for (int j = lane; j < NN; j += 32) s += Arow[j] * gFa[j];
        #pragma unroll
        for (int o = 16; o; o >>= 1) s += __shfl_xor_sync(0xffffffffu, s, o);
        if (lane == 0) gFb[row] = s;
    }
    gbar(&gBar32[bi++]);
    if (tid == 0) {
        float p = 0.0f;
        for (int i = 0; i < 8; i++) { float x = gFb[cta * 8 + i]; p += x * x; }
        gPartF[cta] = p;
    }
    gbar(&gBar32[bi++]);
    if (cta == 0 && tid == 0) {
        float S = 0.0f;
        for (int i = 0; i < PCTAS; i++) S += gPartF[i];
        float lmax = sqrtf(S);
        gLmax = lmax;
        // ---- scaling schedule ----
        float c = CMARGIN * lmax;
        gCval = c;
        double a = 0.9 * (double)EPS / (double)c;
        double b = 0.80;
        for (int k = 0; k < KNS; k++) {
            double lo = 1.0 / b, hi = 2.9999 / b;
            for (int t = 0; t < 30; t++) {
                double s  = 0.5 * (lo + hi);
                double fa = s * a * (3.0 - s * a) * (3.0 - s * a) * 0.25;
                double fb = s * b * (3.0 - s * b) * (3.0 - s * b) * 0.25;
                if (fa < fb) lo = s; else hi = s;
            }
            double s = 0.5 * (lo + hi);
            gS[k] = (float)s;
            double sa = s * a, sb = s * b;
            double fa = sa * (3.0 - sa) * (3.0 - sa) * 0.25;
            double fb = sb * (3.0 - sb) * (3.0 - sb) * 0.25;
            a = fmin(fa, fb);
            b = (sa <= 1.0 && 1.0 <= sb) ? 1.0 : fmax(fa, fb);
            if (a > b) { double tmp = a; a = b; b = tmp; }
        }
    }
}

// Iter-1 shortcut (Z0 = I, Y0 = M'/c implicit): G = sqrt(s)*(1.5I - 0.5*s*M'/c)
__global__ void k_lin1(int g) {
    int idx = blockIdx.x * 256 + threadIdx.x;
    int n = idx >> 10, m = idx & (NN - 1);
    float s  = gS[0];
    float sq = sqrtf(s);
    gBuf[g][idx] = sq * (((n == m) ? 1.5f : 0.0f) - 0.5f * s * gBuf[0][idx] / gCval);
}

// ---------------- SGEMM: C = alpha*A*B + diag*I ----------------

__device__ __forceinline__ void gemm_body(const float* __restrict__ A,
                                          const float* __restrict__ B,
                                          float* __restrict__ C,
                                          float alpha, float diag)
{
    __shared__ float As[16][128];
    __shared__ float Bs[16][64];
    const int tid  = threadIdx.x;
    const int bm   = blockIdx.y << 7;
    const int bn   = blockIdx.x << 6;

    const int arow = tid >> 2;
    const int acol = (tid & 3) << 2;
    const int brow = tid >> 4;
    const int bcol = (tid & 15) << 2;
    const int ty   = tid >> 4;
    const int tx   = tid & 15;

    const float* Aptr = A + (bm + arow) * NN + acol;
    const float* Bptr = B + brow * NN + bn + bcol;

    float4 a0 = *(const float4*)(Aptr);
    float4 a1 = *(const float4*)(Aptr + 64 * NN);
    float4 b0 = *(const float4*)(Bptr);

    float acc[8][4];
    #pragma unroll
    for (int i = 0; i < 8; i++)
        #pragma unroll
        for (int j = 0; j < 4; j++) acc[i][j] = 0.0f;

    for (int kt = 0; kt < NN; kt += 16) {
        As[acol + 0][arow]      = a0.x;
        As[acol + 1][arow]      = a0.y;
        As[acol + 2][arow]      = a0.z;
        As[acol + 3][arow]      = a0.w;
        As[acol + 0][arow + 64] = a1.x;
        As[acol + 1][arow + 64] = a1.y;
        As[acol + 2][arow + 64] = a1.z;
        As[acol + 3][arow + 64] = a1.w;
        *(float4*)&Bs[brow][bcol] = b0;
        __syncthreads();

        if (kt + 16 < NN) {
            a0 = *(const float4*)(Aptr + kt + 16);
            a1 = *(const float4*)(Aptr + 64 * NN + kt + 16);
            b0 = *(const float4*)(Bptr + (kt + 16) * NN);
        }

        #pragma unroll
        for (int k = 0; k < 16; k++) {
            float af[8], bf[4];
            *(float4*)&af[0] = *(const float4*)&As[k][ty << 3];
            *(float4*)&af[4] = *(const float4*)&As[k][(ty << 3) + 4];
            *(float4*)&bf[0] = *(const float4*)&Bs[k][tx << 2];
            #pragma unroll
            for (int i = 0; i < 8; i++)
                #pragma unroll
                for (int j = 0; j < 4; j++)
                    acc[i][j] = fmaf(af[i], bf[j], acc[i][j]);
        }
        __syncthreads();
    }

    const int gc = bn + (tx << 2);
    #pragma unroll
    for (int i = 0; i < 8; i++) {
        int gr = bm + (ty << 3) + i;
        float4 o;
        o.x = alpha * acc[i][0] + ((gr == gc    ) ? diag : 0.0f);
        o.y = alpha * acc[i][1] + ((gr == gc + 1) ? diag : 0.0f);
        o.z = alpha * acc[i][2] + ((gr == gc + 2) ? diag : 0.0f);
        o.w = alpha * acc[i][3] + ((gr == gc + 3) ? diag : 0.0f);
        *(float4*)(C + (size_t)gr * NN + gc) = o;
    }
}

// sidx >= 0: alpha=-0.5*s^1.5, diag=1.5*sqrt(s); sidx==-2: alpha=1/c, diag=0
__global__ void __launch_bounds__(256)
k_gemm(int ia, int ib, int ic, float alpha, float diag, int sidx) {
    float al = alpha, dg = diag;
    if (sidx >= 0) {
        float s  = gS[sidx];
        float sq = sqrtf(s);
        al = -0.5f * s * sq;
        dg = 1.5f * sq;
    } else if (sidx == -2) {
        al = 1.0f / gCval;
        dg = 0.0f;
    }
    gemm_body(gBuf[ia], gBuf[ib], gBuf[ic], al, dg);
}

__global__ void __launch_bounds__(256)
k_gemm_pair(int ia0, int ib0, int ic0, int ia1, int ib1, int ic1) {
    const float* A = gBuf[blockIdx.z ? ia1 : ia0];
    const float* B = gBuf[blockIdx.z ? ib1 : ib0];
    float*       C = gBuf[blockIdx.z ? ic1 : ic0];
    gemm_body(A, B, C, 1.0f, 0.0f);
}

// ---------------- outputs ----------------

// P_k[b] = d_b d_b^T + |P_u| + 0.01*Q^2, d_b[n] = x[n] - x[b*NN+n]
__global__ void k_out1(const float* __restrict__ x,
                       const float* __restrict__ Pu, const float* __restrict__ Qk,
                       float* __restrict__ out) {
    int idx = blockIdx.x * 256 + threadIdx.x;
    int n = idx >> 10, m = idx & (NN - 1);
    float q = Qk[idx];
    float base = fabsf(Pu[idx]) + 0.01f * q * q;
    float x0n = x[n], x0m = x[m];
    #pragma unroll
    for (int b = 0; b < BBATCH; b++) {
        float dn = x0n - x[b * NN + n];
        float dm = x0m - x[b * NN + m];
        out[(size_t)b * NN * NN + idx] = base + dn * dm;
    }
}

// sigma^T[0,b,i,n] = x_b[n] +/- p[i,n];  p = av*v v^T + sqrt(c)*Y - (eps/2)*Z/sqrt(c)
__global__ void k_out2(const float* __restrict__ x, float* __restrict__ out,
                       int iy, int iz) {
    int idx = blockIdx.x * 256 + threadIdx.x;
    int i = idx >> 10, n = idx & (NN - 1);
    float c   = gCval;
    float sqc = sqrtf(c);
    float s2e = sqrtf(2.0f * EPS);
    float av  = sqrtf((float)gLam) - (s2e - EPS / (2.0f * s2e));
    float pv  = av * (float)(gVd[i] * gVd[n])
              + sqc * gBuf[iy][idx]
              - (EPS * 0.5f / sqc) * gBuf[iz][idx];
    #pragma unroll
    for (int b = 0; b < BBATCH; b++) {
        float xb = x[b * NN + n];
        size_t base = (size_t)b * 2 * NN * NN;
        out[base + (size_t)i * NN + n]        = xb + pv;
        out[base + (size_t)(i + NN) * NN + n] = xb - pv;
    }
}

// ---------------- host ----------------

extern "C" void kernel_launch(void* const* d_in, const int* in_sizes, int n_in,
                              void* d_out, int out_size) {
    const float* x  = (const float*)d_in[0];
    const float* Pu = (const float*)d_in[1];
    const float* Qk = (const float*)d_in[2];
    float* out1 = (float*)d_out;
    float* out2 = out1 + (size_t)BBATCH * NN * NN;

    const int EW = NN * NN / 256;
    dim3 gg(NN / 64, NN / 128);
    dim3 gp(NN / 64, NN / 128, 2);

    k_barreset<<<1, 32>>>();
    k_power64<<<PCTAS, PTHR>>>(Pu);
    k_power32<<<PCTAS, PTHR>>>(Pu);   // deflation + power + schedule, fused

    // Scaled Newton-Schulz; iter 1: G1 elementwise, Y1 = (M'/c)*G1 via alpha=1/c
    k_lin1<<<EW, 256>>>(3);
    k_gemm<<<gg, 256>>>(0, 3, 4, 0.0f, 0.0f, -2);
    int Y = 4, Z = 3;
    int f0 = 0, f1 = 1, f2 = 2;
    for (int it = 2; it <= KNS; it++) {
        int G = f0;
        k_gemm<<<gg, 256>>>(Z, Y, G, 0.0f, 0.0f, it - 1);
        if (it < KNS) {
            int Yn = f1, Zn = f2;
            k_gemm_pair<<<gp, 256>>>(Y, G, Yn, G, Z, Zn);
            f0 = Y; f1 = Z; f2 = G;
            Y = Yn; Z = Zn;
        } else {
            int Yn = f1;
            k_gemm<<<gg, 256>>>(Y, G, Yn, 1.0f, 0.0f, -1);
            Y = Yn;
        }
    }

    k_out1<<<EW, 256>>>(x, Pu, Qk, out1);
    k_out2<<<EW, 256>>>(x, out2, Y, Z);
}

// round 16
// speedup vs baseline: 2.3127x; 1.0938x over previous
#include <cuda_runtime.h>
#include <math.h>

#define NN 1024
#define BBATCH 8
#define KNS 8
#define EPS 0.015f
#define CMARGIN 1.4f
#define PCTAS 128
#define PTHR 256

typedef unsigned long long u64t;

__device__ float  gBuf[6][NN * NN];
__device__ double gVd[NN];
__device__ double gLam;
__device__ float  gLmax;
__device__ float  gCval;
__device__ float  gS[KNS];

// persistent power-iteration state
__device__ int    gBar64[16];
__device__ int    gBar32[24];
__device__ double gPartD[PCTAS];
__device__ float  gPartF[PCTAS];
__device__ double gInvD;
__device__ float  gInvF;
__device__ double gVa[NN], gVb[NN];
__device__ float  gFa[NN], gFb[NN];

// ---------------- packed f32x2 helpers (Blackwell FFMA2) ----------------

__device__ __forceinline__ u64t splat2(float v) {
    u64t r; asm("mov.b64 %0, {%1, %1};" : "=l"(r) : "f"(v)); return r;
}
__device__ __forceinline__ void ffma2(u64t& c, u64t a, u64t b) {
    asm("fma.rn.f32x2 %0, %1, %2, %3;" : "=l"(c) : "l"(a), "l"(b), "l"(c));
}
__device__ __forceinline__ void unpack2(u64t v, float& lo, float& hi) {
    asm("mov.b64 {%0, %1}, %2;" : "=f"(lo), "=f"(hi) : "l"(v));
}

// ---------------- global barrier (slot-per-use; slots zeroed each call) -----

__device__ __forceinline__ void gbar(int* slot) {
    __syncthreads();
    if (threadIdx.x == 0) {
        __threadfence();
        atomicAdd(slot, 1);
        volatile int* vs = (volatile int*)slot;
        while (*vs < PCTAS) { __nanosleep(64); }
        __threadfence();
    }
    __syncthreads();
}

__global__ void k_barreset() {
    int t = threadIdx.x;
    if (t < 16) gBar64[t] = 0;
    if (t < 24) gBar32[t] = 0;
}

// Fused fp64 Perron power iteration on M = 1024*|Pu| (read inline from Pu).
__global__ void __launch_bounds__(PTHR, 1) k_power64(const float* __restrict__ Pu) {
    const int cta = blockIdx.x, tid = threadIdx.x;
    const int wid = tid >> 5, lane = tid & 31;
    const int row = cta * 8 + wid;
    int bi = 0;

    if (tid < 8) gVa[cta * 8 + tid] = 1.0 / 32.0;
    gbar(&gBar64[bi++]);

    for (int t = 0; t < 3; t++) {
        const double* vin = (t & 1) ? gVb : gVa;
        double*       vout = (t & 1) ? gVa : gVb;
        const float* Arow = Pu + (size_t)row * NN;
        double s = 0.0;
        #pragma unroll 8
        for (int j = lane; j < NN; j += 32) s += (double)fabsf(Arow[j]) * vin[j];
        #pragma unroll
        for (int o = 16; o; o >>= 1) s += __shfl_xor_sync(0xffffffffu, s, o);
        if (lane == 0) vout[row] = s * 2.0;
        gbar(&gBar64[bi++]);
    }

    if (tid == 0) {
        double p = 0.0;
        for (int i = 0; i < 8; i++) { double x = gVb[cta * 8 + i]; p += x * x; }
        gPartD[cta] = p;
    }
    gbar(&gBar64[bi++]);
    if (cta == 0 && tid == 0) {
        double S = 0.0;
        for (int i = 0; i < PCTAS; i++) S += gPartD[i];
        gInvD = 1.0 / sqrt(S);
    }
    gbar(&gBar64[bi++]);
    if (tid < 8) { int i = cta * 8 + tid; gVa[i] = gVb[i] * gInvD; }
    gbar(&gBar64[bi++]);

    {
        const float* Arow = Pu + (size_t)row * NN;
        double s = 0.0;
        #pragma unroll 8
        for (int j = lane; j < NN; j += 32) s += (double)fabsf(Arow[j]) * gVa[j];
        #pragma unroll
        for (int o = 16; o; o >>= 1) s += __shfl_xor_sync(0xffffffffu, s, o);
        if (lane == 0) gVb[row] = s * 1024.0;
    }
    gbar(&gBar64[bi++]);
    if (tid == 0) {
        double p = 0.0;
        for (int i = 0; i < 8; i++) { double x = gVb[cta * 8 + i]; p += x * x; }
        gPartD[cta] = p;
    }
    gbar(&gBar64[bi++]);
    if (cta == 0 && tid == 0) {
        double S = 0.0;
        for (int i = 0; i < PCTAS; i++) S += gPartD[i];
        double nrm = sqrt(S);
        gLam = nrm;
        gInvD = 1.0 / nrm;
    }
    gbar(&gBar64[bi++]);
    if (tid < 8) { int i = cta * 8 + tid; gVd[i] = gVb[i] * gInvD; }
}

// Fused: deflation + fp32 power iteration on M' + schedule in cta0 tail.
__global__ void __launch_bounds__(PTHR, 1) k_power32(const float* __restrict__ Pu) {
    const int cta = blockIdx.x, tid = threadIdx.x;
    const int wid = tid >> 5, lane = tid & 31;
    const int row = cta * 8 + wid;
    int bi = 0;

    {
        const double lam = gLam - (double)EPS;
        const int base = cta * 8192;
        #pragma unroll 4
        for (int t = tid; t < 8192; t += PTHR) {
            int idx = base + t;
            int n = idx >> 10, m = idx & (NN - 1);
            double val = 1024.0 * (double)fabsf(Pu[idx]) - lam * gVd[n] * gVd[m];
            if (n == m) val += (double)EPS;
            gBuf[0][idx] = (float)val;
        }
        if (tid < 8) {
            unsigned i = (unsigned)(cta * 8 + tid);
            unsigned h = i * 2654435761u + 12345u;
            h ^= h >> 13; h *= 0x5bd1e995u; h ^= h >> 15;
            gFa[i] = (float)(h & 0xFFFFu) / 65536.0f - 0.5f;
        }
    }
    gbar(&gBar32[bi++]);

    for (int t = 0; t < 9; t++) {
        const float* vin  = (t & 1) ? gFb : gFa;
        float*       vout = (t & 1) ? gFa : gFb;
        const float* Arow = &gBuf[0][row * NN];
        float s = 0.0f;
        #pragma unroll 8
        for (int j = lane; j < NN; j += 32) s += Arow[j] * vin[j];
        #pragma unroll
        for (int o = 16; o; o >>= 1) s += __shfl_xor_sync(0xffffffffu, s, o);
        if (lane == 0) vout[row] = s * (1.0f / 512.0f);
        gbar(&gBar32[bi++]);
    }

    if (tid == 0) {
        float p = 0.0f;
        for (int i = 0; i < 8; i++) { float x = gFb[cta * 8 + i]; p += x * x; }
        gPartF[cta] = p;
    }
    gbar(&gBar32[bi++]);
    if (cta == 0 && tid == 0) {
        float S = 0.0f;
        for (int i = 0; i < PCTAS; i++) S += gPartF[i];
        gInvF = 1.0f / sqrtf(S);
    }
    gbar(&gBar32[bi++]);
    if (tid < 8) { int i = cta * 8 + tid; gFa[i] = gFb[i] * gInvF; }
    gbar(&gBar32[bi++]);

    {
        const float* Arow = &gBuf[0][row * NN];
        float s = 0.0f;
        #pragma unroll 8
        for (int j = lane; j < NN; j += 32) s += Arow[j] * gFa[j];
        #pragma unroll
        for (int o = 16; o; o >>= 1) s += __shfl_xor_sync(0xffffffffu, s, o);
        if (lane == 0) gFb[row] = s;
    }
    gbar(&gBar32[bi++]);
    if (tid == 0) {
        float p = 0.0f;
        for (int i = 0; i < 8; i++) { float x = gFb[cta * 8 + i]; p += x * x; }
        gPartF[cta] = p;
    }
    gbar(&gBar32[bi++]);
    if (cta == 0 && tid == 0) {
        float S = 0.0f;
        for (int i = 0; i < PCTAS; i++) S += gPartF[i];
        float lmax = sqrtf(S);
        gLmax = lmax;
        float c = CMARGIN * lmax;
        gCval = c;
        double a = 0.9 * (double)EPS / (double)c;
        double b = 0.80;
        for (int k = 0; k < KNS; k++) {
            double lo = 1.0 / b, hi = 2.9999 / b;
            for (int t = 0; t < 30; t++) {
                double s  = 0.5 * (lo + hi);
                double fa = s * a * (3.0 - s * a) * (3.0 - s * a) * 0.25;
                double fb = s * b * (3.0 - s * b) * (3.0 - s * b) * 0.25;
                if (fa < fb) lo = s; else hi = s;
            }
            double s = 0.5 * (lo + hi);
            gS[k] = (float)s;
            double sa = s * a, sb = s * b;
            double fa = sa * (3.0 - sa) * (3.0 - sa) * 0.25;
            double fb = sb * (3.0 - sb) * (3.0 - sb) * 0.25;
            a = fmin(fa, fb);
            b = (sa <= 1.0 && 1.0 <= sb) ? 1.0 : fmax(fa, fb);
            if (a > b) { double tmp = a; a = b; b = tmp; }
        }
    }
}

// Iter-1 shortcut (Z0 = I, Y0 = M'/c implicit): G = sqrt(s)*(1.5I - 0.5*s*M'/c)
__global__ void k_lin1(int g) {
    int idx = blockIdx.x * 256 + threadIdx.x;
    int n = idx >> 10, m = idx & (NN - 1);
    float s  = gS[0];
    float sq = sqrtf(s);
    gBuf[g][idx] = sq * (((n == m) ? 1.5f : 0.0f) - 0.5f * s * gBuf[0][idx] / gCval);
}

// ---------------- SGEMM via packed f32x2 FMA: C = alpha*A*B + diag*I --------
// BM=128, BN=64, BK=16, 256 threads; accumulators paired along M (ulonglong2
// loads from As give pairs directly); B scalars splatted (4 mov.b64 per k).

__device__ __forceinline__ void gemm_body(const float* __restrict__ A,
                                          const float* __restrict__ B,
                                          float* __restrict__ C,
                                          float alpha, float diag)
{
    __shared__ __align__(16) float As[16][128];
    __shared__ __align__(16) float Bs[16][64];
    const int tid  = threadIdx.x;
    const int bm   = blockIdx.y << 7;
    const int bn   = blockIdx.x << 6;

    const int arow = tid >> 2;
    const int acol = (tid & 3) << 2;
    const int brow = tid >> 4;
    const int bcol = (tid & 15) << 2;
    const int ty   = tid >> 4;
    const int tx   = tid & 15;

    const float* Aptr = A + (bm + arow) * NN + acol;
    const float* Bptr = B + brow * NN + bn + bcol;

    float4 a0 = *(const float4*)(Aptr);
    float4 a1 = *(const float4*)(Aptr + 64 * NN);
    float4 b0 = *(const float4*)(Bptr);

    u64t acc2[4][4];   // [m-pair][n] ; each holds rows (2p, 2p+1)
    #pragma unroll
    for (int p = 0; p < 4; p++)
        #pragma unroll
        for (int j = 0; j < 4; j++) acc2[p][j] = 0ull;

    for (int kt = 0; kt < NN; kt += 16) {
        As[acol + 0][arow]      = a0.x;
        As[acol + 1][arow]      = a0.y;
        As[acol + 2][arow]      = a0.z;
        As[acol + 3][arow]      = a0.w;
        As[acol + 0][arow + 64] = a1.x;
        As[acol + 1][arow + 64] = a1.y;
        As[acol + 2][arow + 64] = a1.z;
        As[acol + 3][arow + 64] = a1.w;
        *(float4*)&Bs[brow][bcol] = b0;
        __syncthreads();

        if (kt + 16 < NN) {
            a0 = *(const float4*)(Aptr + kt + 16);
            a1 = *(const float4*)(Aptr + 64 * NN + kt + 16);
            b0 = *(const float4*)(Bptr + (kt + 16) * NN);
        }

        #pragma unroll
        for (int k = 0; k < 16; k++) {
            ulonglong2 t0 = *(const ulonglong2*)&As[k][ty << 3];
            ulonglong2 t1 = *(const ulonglong2*)&As[k][(ty << 3) + 4];
            u64t af[4] = { t0.x, t0.y, t1.x, t1.y };
            float4 bf = *(const float4*)&Bs[k][tx << 2];
            u64t b2[4] = { splat2(bf.x), splat2(bf.y), splat2(bf.z), splat2(bf.w) };
            #pragma unroll
            for (int p = 0; p < 4; p++)
                #pragma unroll
                for (int j = 0; j < 4; j++)
                    ffma2(acc2[p][j], af[p], b2[j]);
        }
        __syncthreads();
    }

    const int gc = bn + (tx << 2);
    #pragma unroll
    for (int p = 0; p < 4; p++) {
        float r0[4], r1[4];
        #pragma unroll
        for (int j = 0; j < 4; j++) unpack2(acc2[p][j], r0[j], r1[j]);
        const int gr0 = bm + (ty << 3) + 2 * p;
        float4 o0, o1;
        o0.x = alpha * r0[0] + ((gr0     == gc    ) ? diag : 0.0f);
        o0.y = alpha * r0[1] + ((gr0     == gc + 1) ? diag : 0.0f);
        o0.z = alpha * r0[2] + ((gr0     == gc + 2) ? diag : 0.0f);
        o0.w = alpha * r0[3] + ((gr0     == gc + 3) ? diag : 0.0f);
        o1.x = alpha * r1[0] + ((gr0 + 1 == gc    ) ? diag : 0.0f);
        o1.y = alpha * r1[1] + ((gr0 + 1 == gc + 1) ? diag : 0.0f);
        o1.z = alpha * r1[2] + ((gr0 + 1 == gc + 2) ? diag : 0.0f);
        o1.w = alpha * r1[3] + ((gr0 + 1 == gc + 3) ? diag : 0.0f);
        *(float4*)(C + (size_t)gr0 * NN + gc)       = o0;
        *(float4*)(C + (size_t)(gr0 + 1) * NN + gc) = o1;
    }
}

// sidx >= 0: alpha=-0.5*s^1.5, diag=1.5*sqrt(s); sidx==-2: alpha=1/c, diag=0
__global__ void __launch_bounds__(256)
k_gemm(int ia, int ib, int ic, float alpha, float diag, int sidx) {
    float al = alpha, dg = diag;
    if (sidx >= 0) {
        float s  = gS[sidx];
        float sq = sqrtf(s);
        al = -0.5f * s * sq;
        dg = 1.5f * sq;
    } else if (sidx == -2) {
        al = 1.0f / gCval;
        dg = 0.0f;
    }
    gemm_body(gBuf[ia], gBuf[ib], gBuf[ic], al, dg);
}

__global__ void __launch_bounds__(256)
k_gemm_pair(int ia0, int ib0, int ic0, int ia1, int ib1, int ic1) {
    const float* A = gBuf[blockIdx.z ? ia1 : ia0];
    const float* B = gBuf[blockIdx.z ? ib1 : ib0];
    float*       C = gBuf[blockIdx.z ? ic1 : ic0];
    gemm_body(A, B, C, 1.0f, 0.0f);
}

// ---------------- outputs ----------------

__global__ void k_out1(const float* __restrict__ x,
                       const float* __restrict__ Pu, const float* __restrict__ Qk,
                       float* __restrict__ out) {
    int idx = blockIdx.x * 256 + threadIdx.x;
    int n = idx >> 10, m = idx & (NN - 1);
    float q = Qk[idx];
    float base = fabsf(Pu[idx]) + 0.01f * q * q;
    float x0n = x[n], x0m = x[m];
    #pragma unroll
    for (int b = 0; b < BBATCH; b++) {
        float dn = x0n - x[b * NN + n];
        float dm = x0m - x[b * NN + m];
        out[(size_t)b * NN * NN + idx] = base + dn * dm;
    }
}

__global__ void k_out2(const float* __restrict__ x, float* __restrict__ out,
                       int iy, int iz) {
    int idx = blockIdx.x * 256 + threadIdx.x;
    int i = idx >> 10, n = idx & (NN - 1);
    float c   = gCval;
    float sqc = sqrtf(c);
    float s2e = sqrtf(2.0f * EPS);
    float av  = sqrtf((float)gLam) - (s2e - EPS / (2.0f * s2e));
    float pv  = av * (float)(gVd[i] * gVd[n])
              + sqc * gBuf[iy][idx]
              - (EPS * 0.5f / sqc) * gBuf[iz][idx];
    #pragma unroll
    for (int b = 0; b < BBATCH; b++) {
        float xb = x[b * NN + n];
        size_t base = (size_t)b * 2 * NN * NN;
        out[base + (size_t)i * NN + n]        = xb + pv;
        out[base + (size_t)(i + NN) * NN + n] = xb - pv;
    }
}

// ---------------- host ----------------

extern "C" void kernel_launch(void* const* d_in, const int* in_sizes, int n_in,
                              void* d_out, int out_size) {
    const float* x  = (const float*)d_in[0];
    const float* Pu = (const float*)d_in[1];
    const float* Qk = (const float*)d_in[2];
    float* out1 = (float*)d_out;
    float* out2 = out1 + (size_t)BBATCH * NN * NN;

    const int EW = NN * NN / 256;
    dim3 gg(NN / 64, NN / 128);
    dim3 gp(NN / 64, NN / 128, 2);

    k_barreset<<<1, 32>>>();
    k_power64<<<PCTAS, PTHR>>>(Pu);
    k_power32<<<PCTAS, PTHR>>>(Pu);   // deflation + power + schedule, fused

    k_lin1<<<EW, 256>>>(3);
    k_gemm<<<gg, 256>>>(0, 3, 4, 0.0f, 0.0f, -2);
    int Y = 4, Z = 3;
    int f0 = 0, f1 = 1, f2 = 2;
    for (int it = 2; it <= KNS; it++) {
        int G = f0;
        k_gemm<<<gg, 256>>>(Z, Y, G, 0.0f, 0.0f, it - 1);
        if (it < KNS) {
            int Yn = f1, Zn = f2;
            k_gemm_pair<<<gp, 256>>>(Y, G, Yn, G, Z, Zn);
            f0 = Y; f1 = Z; f2 = G;
            Y = Yn; Z = Zn;
        } else {
            int Yn = f1;
            k_gemm<<<gg, 256>>>(Y, G, Yn, 1.0f, 0.0f, -1);
            Y = Yn;
        }
    }

    k_out1<<<EW, 256>>>(x, Pu, Qk, out1);
    k_out2<<<EW, 256>>>(x, out2, Y, Z);
}